// round 1
// baseline (speedup 1.0000x reference)
#include <cuda_runtime.h>
#include <math.h>

// Problem constants
#define BB 4
#define TT 4096
#define DM 1024
#define NH 16
#define DH 64
#define HV 128
#define NDIM1 4128            // 2*KEY_DIM + VALUE_DIM + 2*N_HEADS
#define NDIM2 2048            // N_HEADS * HEAD_V
#define MM (BB*TT)            // 16384
#define KK DM                 // 1024

// Scratch (no cudaMalloc allowed)
__device__ float g_qkvba[(size_t)MM * NDIM1];     // 270 MB
__device__ float g_gate [(size_t)MM * NDIM2];     // 134 MB
__device__ float g_q [(size_t)BB*NH*TT*DH];       // 67 MB
__device__ float g_k [(size_t)BB*NH*TT*DH];       // 67 MB
__device__ float g_v [(size_t)BB*NH*TT*HV];       // 134 MB
__device__ float g_eg[(size_t)BB*NH*TT];
__device__ float g_be[(size_t)BB*NH*TT];

// ---------------------------------------------------------------------------
// SGEMM: C[M,N] = A[M,K] @ B[K,N], fp32, 128x128x8 block tile, 8x8 per thread
// ---------------------------------------------------------------------------
template <int N>
__device__ __forceinline__ void sgemm_body(const float* __restrict__ A,
                                           const float* __restrict__ Bm,
                                           float* __restrict__ C) {
    __shared__ float As[8][128];
    __shared__ float Bs[8][128];
    int tid = threadIdx.x;
    int tx = tid & 15;         // 0..15 -> N
    int ty = tid >> 4;         // 0..15 -> M
    int m0 = blockIdx.y * 128;
    int n0 = blockIdx.x * 128;
    int arow = tid >> 1, acol = (tid & 1) * 4;   // A tile loader: 128x8
    int brow = tid >> 5, bcol = (tid & 31) * 4;  // B tile loader: 8x128

    float acc[8][8];
#pragma unroll
    for (int i = 0; i < 8; i++)
#pragma unroll
        for (int j = 0; j < 8; j++) acc[i][j] = 0.f;

    for (int k0 = 0; k0 < KK; k0 += 8) {
        float4 av = *(const float4*)&A[(size_t)(m0 + arow) * KK + k0 + acol];
        As[acol + 0][arow] = av.x;
        As[acol + 1][arow] = av.y;
        As[acol + 2][arow] = av.z;
        As[acol + 3][arow] = av.w;
        float4 bv = make_float4(0.f, 0.f, 0.f, 0.f);
        if (n0 + bcol < N)
            bv = *(const float4*)&Bm[(size_t)(k0 + brow) * N + n0 + bcol];
        *(float4*)&Bs[brow][bcol] = bv;
        __syncthreads();
#pragma unroll
        for (int kk = 0; kk < 8; kk++) {
            float a[8], b[8];
#pragma unroll
            for (int i = 0; i < 8; i++) a[i] = As[kk][ty * 8 + i];
#pragma unroll
            for (int j = 0; j < 8; j++) b[j] = Bs[kk][tx * 8 + j];
#pragma unroll
            for (int i = 0; i < 8; i++)
#pragma unroll
                for (int j = 0; j < 8; j++)
                    acc[i][j] = fmaf(a[i], b[j], acc[i][j]);
        }
        __syncthreads();
    }
#pragma unroll
    for (int i = 0; i < 8; i++) {
        int row = m0 + ty * 8 + i;
#pragma unroll
        for (int j = 0; j < 8; j++) {
            int col = n0 + tx * 8 + j;
            if (col < N) C[(size_t)row * N + col] = acc[i][j];
        }
    }
}

__global__ void __launch_bounds__(256) gemm_in_kernel(const float* __restrict__ A,
                                                      const float* __restrict__ W) {
    sgemm_body<NDIM1>(A, W, g_qkvba);
}
__global__ void __launch_bounds__(256) gemm_gate_kernel(const float* __restrict__ A,
                                                        const float* __restrict__ W) {
    sgemm_body<NDIM2>(A, W, g_gate);
}

// ---------------------------------------------------------------------------
// Prep: causal conv4 + SiLU on q/k/v, l2norm on q/k, beta/exp(g)
// one block per (b, t), 256 threads
// ---------------------------------------------------------------------------
__device__ __forceinline__ float silu_f(float y) { return y / (1.f + expf(-y)); }

__global__ void __launch_bounds__(256) prep_kernel(const float* __restrict__ qw,
                                                   const float* __restrict__ kw,
                                                   const float* __restrict__ vw,
                                                   const float* __restrict__ dtb,
                                                   const float* __restrict__ Alog) {
    __shared__ float sq[1024];
    __shared__ float sk[1024];
    __shared__ float sscale[32];
    int row = blockIdx.x;
    int b = row / TT, t = row % TT;
    int tid = threadIdx.x;
    const float* base = g_qkvba + (size_t)row * NDIM1;

    // q and k: conv + silu into shared
#pragma unroll
    for (int r = 0; r < 4; r++) {
        int c = tid + r * 256;
        float yq = 0.f, yk = 0.f;
#pragma unroll
        for (int i = 0; i < 4; i++) {
            int tt = t - 3 + i;
            if (tt >= 0) {
                const float* xr = base + (size_t)(i - 3) * NDIM1;
                yq = fmaf(xr[c], qw[c * 4 + i], yq);
                yk = fmaf(xr[1024 + c], kw[c * 4 + i], yk);
            }
        }
        sq[c] = silu_f(yq);
        sk[c] = silu_f(yk);
    }
    // v: conv + silu, write directly
#pragma unroll
    for (int r = 0; r < 8; r++) {
        int cv = tid + r * 256;
        float yv = 0.f;
#pragma unroll
        for (int i = 0; i < 4; i++) {
            int tt = t - 3 + i;
            if (tt >= 0)
                yv = fmaf(base[(size_t)(i - 3) * NDIM1 + 2048 + cv], vw[cv * 4 + i], yv);
        }
        int h = cv >> 7, j = cv & 127;
        g_v[(((size_t)(b * NH + h)) * TT + t) * HV + j] = silu_f(yv);
    }
    __syncthreads();
    // per-head l2norm scales
    if (tid < 16) {
        float s = 0.f;
#pragma unroll
        for (int d = 0; d < 64; d++) { float x = sq[tid * 64 + d]; s = fmaf(x, x, s); }
        sscale[tid] = rsqrtf(s + 1e-6f) * 0.125f;   // includes D_HEAD^-0.5
    } else if (tid < 32) {
        int h = tid - 16;
        float s = 0.f;
#pragma unroll
        for (int d = 0; d < 64; d++) { float x = sk[h * 64 + d]; s = fmaf(x, x, s); }
        sscale[tid] = rsqrtf(s + 1e-6f);
    }
    // beta / exp(g)
    if (tid < 16) {
        int h = tid;
        float bp = base[4096 + h];
        float ap = base[4112 + h];
        float beta = 1.f / (1.f + expf(-bp));
        float x = ap + dtb[h];
        float sp = (x > 20.f) ? x : log1pf(expf(x));
        float g = -expf(Alog[h]) * sp;
        size_t idx = (size_t)(b * NH + h) * TT + t;
        g_eg[idx] = expf(g);
        g_be[idx] = beta;
    }
    __syncthreads();
    // write normalized q, k
#pragma unroll
    for (int r = 0; r < 4; r++) {
        int c = tid + r * 256;
        int h = c >> 6, d = c & 63;
        size_t idx = (((size_t)(b * NH + h)) * TT + t) * DH + d;
        g_q[idx] = sq[c] * sscale[h];
        g_k[idx] = sk[c] * sscale[16 + h];
    }
}

// ---------------------------------------------------------------------------
// Scan: one block per (b,h), 128 threads; thread j owns state column S[:,j]
// Fuses the output gating: out = o * silu(gate)
// ---------------------------------------------------------------------------
__global__ void __launch_bounds__(128) scan_kernel(float* __restrict__ out) {
    __shared__ float skb[2][64];
    __shared__ float sqb[2][64];
    __shared__ float seg[2], sbe[2];
    int bh = blockIdx.x;
    int b = bh >> 4, h = bh & 15;
    int j = threadIdx.x;
    const float* qp = g_q + (size_t)bh * TT * DH;
    const float* kp = g_k + (size_t)bh * TT * DH;
    const float* vp = g_v + (size_t)bh * TT * HV + j;
    const float* egp = g_eg + (size_t)bh * TT;
    const float* bep = g_be + (size_t)bh * TT;
    const float* gp = g_gate + (size_t)b * TT * NDIM2 + h * HV + j; // stride NDIM2 per t
    float* op = out + (size_t)b * TT * NDIM2 + h * HV + j;          // same layout

    float S[64];
#pragma unroll
    for (int d = 0; d < 64; d++) S[d] = 0.f;

    // preload t = 0
    if (j < 64) skb[0][j] = kp[j]; else sqb[0][j - 64] = qp[j - 64];
    if (j == 0) { seg[0] = egp[0]; sbe[0] = bep[0]; }
    __syncthreads();
    float vcur = vp[0];
    float gcur = gp[0];

    for (int t = 0; t < TT; t++) {
        int cur = t & 1, nxt = cur ^ 1;
        // prefetch t+1
        if (t + 1 < TT) {
            if (j < 64) skb[nxt][j] = kp[(size_t)(t + 1) * 64 + j];
            else        sqb[nxt][j - 64] = qp[(size_t)(t + 1) * 64 + (j - 64)];
            if (j == 0) { seg[nxt] = egp[t + 1]; sbe[nxt] = bep[t + 1]; }
        }
        float vnx = (t + 1 < TT) ? vp[(size_t)(t + 1) * HV] : 0.f;
        float gnx = (t + 1 < TT) ? gp[(size_t)(t + 1) * NDIM2] : 0.f;

        float eg = seg[cur], be = sbe[cur];

        // kS = k . S_old  (4 accumulators to shorten the dependency chain)
        float a0 = 0.f, a1 = 0.f, a2 = 0.f, a3 = 0.f;
#pragma unroll
        for (int d = 0; d < 64; d += 4) {
            float4 kk = *(const float4*)&skb[cur][d];
            a0 = fmaf(kk.x, S[d + 0], a0);
            a1 = fmaf(kk.y, S[d + 1], a1);
            a2 = fmaf(kk.z, S[d + 2], a2);
            a3 = fmaf(kk.w, S[d + 3], a3);
        }
        float kS = (a0 + a1) + (a2 + a3);
        float vnew = (vcur - eg * kS) * be;

        // state update + output projection
        float o0 = 0.f, o1 = 0.f, o2 = 0.f, o3 = 0.f;
#pragma unroll
        for (int d = 0; d < 64; d += 4) {
            float4 kk = *(const float4*)&skb[cur][d];
            float4 qq = *(const float4*)&sqb[cur][d];
            S[d + 0] = fmaf(kk.x, vnew, S[d + 0] * eg); o0 = fmaf(qq.x, S[d + 0], o0);
            S[d + 1] = fmaf(kk.y, vnew, S[d + 1] * eg); o1 = fmaf(qq.y, S[d + 1], o1);
            S[d + 2] = fmaf(kk.z, vnew, S[d + 2] * eg); o2 = fmaf(qq.z, S[d + 2], o2);
            S[d + 3] = fmaf(kk.w, vnew, S[d + 3] * eg); o3 = fmaf(qq.w, S[d + 3], o3);
        }
        float o = (o0 + o1) + (o2 + o3);

        float sg = gcur / (1.f + expf(-gcur));   // silu(gate)
        op[(size_t)t * NDIM2] = o * sg;

        vcur = vnx; gcur = gnx;
        __syncthreads();
    }
}

// ---------------------------------------------------------------------------
extern "C" void kernel_launch(void* const* d_in, const int* in_sizes, int n_in,
                              void* d_out, int out_size) {
    const float* H    = (const float*)d_in[0];
    const float* Win  = (const float*)d_in[1];
    const float* qw   = (const float*)d_in[2];
    const float* kw   = (const float*)d_in[3];
    const float* vw   = (const float*)d_in[4];
    const float* dtb  = (const float*)d_in[5];
    const float* Alog = (const float*)d_in[6];
    const float* Wg   = (const float*)d_in[7];
    float* out = (float*)d_out;

    dim3 g1((NDIM1 + 127) / 128, MM / 128);
    gemm_in_kernel<<<g1, 256>>>(H, Win);
    dim3 g2((NDIM2 + 127) / 128, MM / 128);
    gemm_gate_kernel<<<g2, 256>>>(H, Wg);
    prep_kernel<<<MM, 256>>>(qw, kw, vw, dtb, Alog);
    scan_kernel<<<BB * NH, 128>>>(out);
}

// round 5
// speedup vs baseline: 1.5564x; 1.5564x over previous
#include <cuda_runtime.h>
#include <math.h>
#include <cstdint>

// ---------------------------------------------------------------------------
// Problem constants
// ---------------------------------------------------------------------------
#define BB 4
#define TT 4096
#define NH 16
#define DH 64
#define HV 128
#define NDIM1 4128            // 2*KEY_DIM + VALUE_DIM + 2*N_HEADS
#define NDIM2 2048            // N_HEADS * HEAD_V
#define MM (BB*TT)            // 16384
#define KK 1024
#define N1PAD 4224            // 33 * 128 (padded for N-tiling)

#define GM_SMEM 73728         // 2 buffers x (A 18432 + B 18432)

// ---------------------------------------------------------------------------
// Scratch (no cudaMalloc allowed)
// ---------------------------------------------------------------------------
__device__ float g_qkvba[(size_t)MM * NDIM1];
__device__ float g_gate [(size_t)MM * NDIM2];
__device__ float g_q [(size_t)BB*NH*TT*DH];
__device__ float g_k [(size_t)BB*NH*TT*DH];
__device__ float g_v [(size_t)BB*NH*TT*HV];
__device__ float g_eg[(size_t)BB*NH*TT];
__device__ float g_be[(size_t)BB*NH*TT];
__device__ float g_a32    [(size_t)MM * KK];       // tf32-rounded, k-permuted A
__device__ float g_wt_in  [(size_t)N1PAD * KK];    // tf32-rounded, k-permuted W_in^T
__device__ float g_wt_gate[(size_t)NDIM2 * KK];    // tf32-rounded, k-permuted W_gate^T

// ---------------------------------------------------------------------------
// Helpers
// ---------------------------------------------------------------------------
__device__ __forceinline__ uint32_t smem_u32(const void* p) {
    uint32_t a;
    asm("{ .reg .u64 t; cvta.to.shared.u64 t, %1; cvt.u32.u64 %0, t; }" : "=r"(a) : "l"(p));
    return a;
}
// cvt.rna.tf32.f32 requires a .b32 destination register -> "=r" constraint
__device__ __forceinline__ float to_tf32(float x) {
    uint32_t r; asm("cvt.rna.tf32.f32 %0, %1;" : "=r"(r) : "f"(x));
    return __uint_as_float(r);
}
// within-8 k permutation: pair (c, c+4) becomes adjacent
__device__ __forceinline__ int kperm(int c) {
    return (c & ~7) | ((c & 3) << 1) | ((c >> 2) & 1);
}
__device__ __forceinline__ void cpa16(uint32_t dst, const void* src) {
    asm volatile("cp.async.cg.shared.global [%0], [%1], 16;" :: "r"(dst), "l"(src) : "memory");
}
__device__ __forceinline__ void cpa_commit() {
    asm volatile("cp.async.commit_group;" ::: "memory");
}

// tf32 mma m16n8k8, row.col, f32 accum (base ISA, sm_80+)
__device__ __forceinline__ void mma_tf32(float* d, const uint32_t* a, const uint32_t* b) {
    asm volatile(
        "mma.sync.aligned.m16n8k8.row.col.f32.tf32.tf32.f32 "
        "{%0,%1,%2,%3}, {%4,%5,%6,%7}, {%8,%9}, {%0,%1,%2,%3};"
        : "+f"(d[0]), "+f"(d[1]), "+f"(d[2]), "+f"(d[3])
        : "r"(a[0]), "r"(a[1]), "r"(a[2]), "r"(a[3]), "r"(b[0]), "r"(b[1]));
}

// f32x2 packed math (base ISA on sm_100)
typedef unsigned long long ull;
__device__ __forceinline__ ull fma2q(ull a, ull b, ull c) {
    ull d; asm("fma.rn.f32x2 %0, %1, %2, %3;" : "=l"(d) : "l"(a), "l"(b), "l"(c)); return d;
}
__device__ __forceinline__ ull mul2q(ull a, ull b) {
    ull d; asm("mul.rn.f32x2 %0, %1, %2;" : "=l"(d) : "l"(a), "l"(b)); return d;
}
__device__ __forceinline__ ull pack2q(float a, float b) {
    ull r; asm("mov.b64 %0, {%1, %2};" : "=l"(r) : "f"(a), "f"(b)); return r;
}
__device__ __forceinline__ float2 unpack2q(ull v) {
    float2 r; asm("mov.b64 {%0, %1}, %2;" : "=f"(r.x), "=f"(r.y) : "l"(v)); return r;
}

// ---------------------------------------------------------------------------
// A pre-pass: tf32 round + k-permute  (g_a32[row][kperm(c)] = tf32(H[row][c]))
// ---------------------------------------------------------------------------
__global__ void __launch_bounds__(256) around_kernel(const float* __restrict__ H) {
    size_t row = blockIdx.x;
    const float* src = H + row * KK;
    float* dst = g_a32 + row * KK;
#pragma unroll
    for (int r = 0; r < 4; r++) {
        int c = threadIdx.x + r * 256;
        dst[kperm(c)] = to_tf32(src[c]);
    }
}

// ---------------------------------------------------------------------------
// Weight transpose: Wt[n][kperm(k)] = tf32(W[k][n]), zero-padded rows
// ---------------------------------------------------------------------------
__global__ void __launch_bounds__(256) transpose_kernel(const float* __restrict__ W,
                                                        float* __restrict__ Wt, int N) {
    __shared__ float tile[32][33];
    int k0 = blockIdx.x * 32, n0 = blockIdx.y * 32;
    int tx = threadIdx.x & 31, ty = threadIdx.x >> 5;   // 32 x 8
#pragma unroll
    for (int i = 0; i < 32; i += 8) {
        int n = n0 + tx;
        float v = (n < N) ? W[(size_t)(k0 + ty + i) * N + n] : 0.f;
        tile[ty + i][tx] = to_tf32(v);
    }
    __syncthreads();
#pragma unroll
    for (int i = 0; i < 32; i += 8)
        Wt[(size_t)(n0 + ty + i) * KK + kperm(k0 + tx)] = tile[tx][ty + i];
}

// ---------------------------------------------------------------------------
// tf32 mma.sync GEMM: C[M,NC] = A[M,1024] @ Bt[n,1024]^T
// CTA 128x128, K-chunk 32, cp.async double buffer, 8 warps (32x64 each)
// ---------------------------------------------------------------------------
__global__ void __launch_bounds__(256) gemm_mma(const float* __restrict__ A,
                                                const float* __restrict__ Bt,
                                                float* __restrict__ C, int NC) {
    extern __shared__ float smf[];                 // [2][A:128x36 | B:128x36]
    uint32_t sbase = smem_u32(smf);

    int tid = threadIdx.x;
    int lane = tid & 31, wid = tid >> 5;
    int gid = lane >> 2, tig = lane & 3;
    int wm = wid & 3, wn = wid >> 2;               // 4 x 2 warp grid
    int m0 = blockIdx.y * 128;
    int n0 = blockIdx.x * 128;

    float acc[2][8][4];
#pragma unroll
    for (int mt = 0; mt < 2; mt++)
#pragma unroll
        for (int nt = 0; nt < 8; nt++)
#pragma unroll
            for (int i = 0; i < 4; i++) acc[mt][nt][i] = 0.f;

    const float* aBase = A  + (size_t)m0 * KK;
    const float* bBase = Bt + (size_t)n0 * KK;

    // stage chunk ch into buffer b
    auto load_tile = [&](int ch, int b) {
        uint32_t a_dst = sbase + b * 36864u;
        uint32_t b_dst = a_dst + 18432u;
        const float* aS = aBase + ch * 32;
        const float* bS = bBase + ch * 32;
#pragma unroll
        for (int i = 0; i < 4; i++) {
            int id = tid + 256 * i;
            int row = id >> 3, seg = id & 7;
            cpa16(a_dst + row * 144u + seg * 16u, aS + (size_t)row * KK + seg * 4);
            cpa16(b_dst + row * 144u + seg * 16u, bS + (size_t)row * KK + seg * 4);
        }
        cpa_commit();
    };

    load_tile(0, 0);
    for (int ch = 0; ch < KK / 32; ch++) {
        if (ch + 1 < KK / 32) load_tile(ch + 1, (ch + 1) & 1);
        if (ch + 1 < KK / 32) asm volatile("cp.async.wait_group 1;" ::: "memory");
        else                  asm volatile("cp.async.wait_group 0;" ::: "memory");
        __syncthreads();

        const float* As_f = smf + (ch & 1) * 9216;
        const float* Bs_f = As_f + 4608;
        const float* aW = As_f + (wm * 32 + gid) * 36 + 2 * tig;
        const float* bW = Bs_f + (wn * 64 + gid) * 36 + 2 * tig;

#pragma unroll
        for (int ks = 0; ks < 4; ks++) {
            uint32_t af[2][4];
#pragma unroll
            for (int mt = 0; mt < 2; mt++) {
                float2 v0 = *(const float2*)(aW + (mt * 16) * 36 + ks * 8);
                float2 v1 = *(const float2*)(aW + (mt * 16 + 8) * 36 + ks * 8);
                af[mt][0] = __float_as_uint(v0.x);
                af[mt][2] = __float_as_uint(v0.y);
                af[mt][1] = __float_as_uint(v1.x);
                af[mt][3] = __float_as_uint(v1.y);
            }
            uint32_t bf[8][2];
#pragma unroll
            for (int nt = 0; nt < 8; nt++) {
                float2 v = *(const float2*)(bW + (nt * 8) * 36 + ks * 8);
                bf[nt][0] = __float_as_uint(v.x);
                bf[nt][1] = __float_as_uint(v.y);
            }
#pragma unroll
            for (int mt = 0; mt < 2; mt++)
#pragma unroll
                for (int nt = 0; nt < 8; nt++)
                    mma_tf32(acc[mt][nt], af[mt], bf[nt]);
        }
        __syncthreads();
    }

    // epilogue
#pragma unroll
    for (int mt = 0; mt < 2; mt++) {
        int row = m0 + wm * 32 + mt * 16 + gid;
#pragma unroll
        for (int nt = 0; nt < 8; nt++) {
            int col = n0 + wn * 64 + nt * 8 + 2 * tig;
            if (col < NC) {
                *(float2*)&C[(size_t)row * NC + col] =
                    make_float2(acc[mt][nt][0], acc[mt][nt][1]);
                *(float2*)&C[(size_t)(row + 8) * NC + col] =
                    make_float2(acc[mt][nt][2], acc[mt][nt][3]);
            }
        }
    }
}

// ---------------------------------------------------------------------------
// Prep: causal conv4 + SiLU on q/k/v, l2norm on q/k, beta/exp(g)
// ---------------------------------------------------------------------------
__device__ __forceinline__ float silu_f(float y) { return y / (1.f + expf(-y)); }

__global__ void __launch_bounds__(256) prep_kernel(const float* __restrict__ qw,
                                                   const float* __restrict__ kw,
                                                   const float* __restrict__ vw,
                                                   const float* __restrict__ dtb,
                                                   const float* __restrict__ Alog) {
    __shared__ float sq[1024];
    __shared__ float sk[1024];
    __shared__ float sscale[32];
    int row = blockIdx.x;
    int b = row / TT, t = row % TT;
    int tid = threadIdx.x;
    const float* base = g_qkvba + (size_t)row * NDIM1;

#pragma unroll
    for (int r = 0; r < 4; r++) {
        int c = tid + r * 256;
        float yq = 0.f, yk = 0.f;
#pragma unroll
        for (int i = 0; i < 4; i++) {
            int tt = t - 3 + i;
            if (tt >= 0) {
                const float* xr = base + (size_t)(i - 3) * NDIM1;
                yq = fmaf(xr[c], qw[c * 4 + i], yq);
                yk = fmaf(xr[1024 + c], kw[c * 4 + i], yk);
            }
        }
        sq[c] = silu_f(yq);
        sk[c] = silu_f(yk);
    }
#pragma unroll
    for (int r = 0; r < 8; r++) {
        int cv = tid + r * 256;
        float yv = 0.f;
#pragma unroll
        for (int i = 0; i < 4; i++) {
            int tt = t - 3 + i;
            if (tt >= 0)
                yv = fmaf(base[(size_t)(i - 3) * NDIM1 + 2048 + cv], vw[cv * 4 + i], yv);
        }
        int h = cv >> 7, j = cv & 127;
        g_v[(((size_t)(b * NH + h)) * TT + t) * HV + j] = silu_f(yv);
    }
    __syncthreads();
    if (tid < 16) {
        float s = 0.f;
#pragma unroll
        for (int d = 0; d < 64; d++) { float x = sq[tid * 64 + d]; s = fmaf(x, x, s); }
        sscale[tid] = rsqrtf(s + 1e-6f) * 0.125f;
    } else if (tid < 32) {
        int h = tid - 16;
        float s = 0.f;
#pragma unroll
        for (int d = 0; d < 64; d++) { float x = sk[h * 64 + d]; s = fmaf(x, x, s); }
        sscale[tid] = rsqrtf(s + 1e-6f);
    }
    if (tid < 16) {
        int h = tid;
        float bp = base[4096 + h];
        float ap = base[4112 + h];
        float beta = 1.f / (1.f + expf(-bp));
        float x = ap + dtb[h];
        float sp = (x > 20.f) ? x : log1pf(expf(x));
        float g = -expf(Alog[h]) * sp;
        size_t idx = (size_t)(b * NH + h) * TT + t;
        g_eg[idx] = expf(g);
        g_be[idx] = beta;
    }
    __syncthreads();
#pragma unroll
    for (int r = 0; r < 4; r++) {
        int c = tid + r * 256;
        int h = c >> 6, d = c & 63;
        size_t idx = (((size_t)(b * NH + h)) * TT + t) * DH + d;
        g_q[idx] = sq[c] * sscale[h];
        g_k[idx] = sk[c] * sscale[16 + h];
    }
}

// ---------------------------------------------------------------------------
// Scan: one block per (b,h), 128 threads, thread j owns S[:,j]; f32x2 math
// ---------------------------------------------------------------------------
__global__ void __launch_bounds__(128) scan_kernel(float* __restrict__ out) {
    __shared__ __align__(16) float skb[2][64];
    __shared__ __align__(16) float sqb[2][64];
    __shared__ float seg[2], sbe[2];
    int bh = blockIdx.x;
    int b = bh >> 4, h = bh & 15;
    int j = threadIdx.x;
    const float* qp  = g_q  + (size_t)bh * TT * DH;
    const float* kp  = g_k  + (size_t)bh * TT * DH;
    const float* vp  = g_v  + (size_t)bh * TT * HV + j;
    const float* egp = g_eg + (size_t)bh * TT;
    const float* bep = g_be + (size_t)bh * TT;
    const float* gp  = g_gate + (size_t)b * TT * NDIM2 + h * HV + j;
    float* op        = out    + (size_t)b * TT * NDIM2 + h * HV + j;

    ull S2[32];
#pragma unroll
    for (int d = 0; d < 32; d++) S2[d] = 0ULL;

    if (j < 64) skb[0][j] = kp[j]; else sqb[0][j - 64] = qp[j - 64];
    if (j == 0) { seg[0] = egp[0]; sbe[0] = bep[0]; }
    __syncthreads();
    float vcur = vp[0];
    float gcur = gp[0];

    for (int t = 0; t < TT; t++) {
        int cur = t & 1, nxt = cur ^ 1;
        if (t + 1 < TT) {
            if (j < 64) skb[nxt][j] = kp[(size_t)(t + 1) * 64 + j];
            else        sqb[nxt][j - 64] = qp[(size_t)(t + 1) * 64 + (j - 64)];
            if (j == 0) { seg[nxt] = egp[t + 1]; sbe[nxt] = bep[t + 1]; }
        }
        float vnx = (t + 1 < TT) ? vp[(size_t)(t + 1) * HV] : 0.f;
        float gnx = (t + 1 < TT) ? gp[(size_t)(t + 1) * NDIM2] : 0.f;

        float eg = seg[cur], be = sbe[cur];
        const ulonglong2* k2p = (const ulonglong2*)skb[cur];
        const ulonglong2* q2p = (const ulonglong2*)sqb[cur];

        ull a0 = 0, a1 = 0, a2 = 0, a3 = 0;
#pragma unroll
        for (int i = 0; i < 8; i++) {
            ulonglong2 ka = k2p[i];
            ulonglong2 kb = k2p[i + 8];
            a0 = fma2q(ka.x, S2[2 * i],      a0);
            a1 = fma2q(ka.y, S2[2 * i + 1],  a1);
            a2 = fma2q(kb.x, S2[2 * i + 16], a2);
            a3 = fma2q(kb.y, S2[2 * i + 17], a3);
        }
        float2 u0 = unpack2q(a0), u1 = unpack2q(a1), u2 = unpack2q(a2), u3 = unpack2q(a3);
        float kS = ((u0.x + u0.y) + (u1.x + u1.y)) + ((u2.x + u2.y) + (u3.x + u3.y));
        float vnew = (vcur - eg * kS) * be;

        ull eg2 = pack2q(eg, eg);
        ull vn2 = pack2q(vnew, vnew);
        ull o0 = 0, o1 = 0, o2 = 0, o3 = 0;
#pragma unroll
        for (int i = 0; i < 8; i++) {
            ulonglong2 ka = k2p[i],  kb = k2p[i + 8];
            ulonglong2 qa = q2p[i],  qb = q2p[i + 8];
            S2[2 * i]      = fma2q(ka.x, vn2, mul2q(S2[2 * i],      eg2)); o0 = fma2q(qa.x, S2[2 * i],      o0);
            S2[2 * i + 1]  = fma2q(ka.y, vn2, mul2q(S2[2 * i + 1],  eg2)); o1 = fma2q(qa.y, S2[2 * i + 1],  o1);
            S2[2 * i + 16] = fma2q(kb.x, vn2, mul2q(S2[2 * i + 16], eg2)); o2 = fma2q(qb.x, S2[2 * i + 16], o2);
            S2[2 * i + 17] = fma2q(kb.y, vn2, mul2q(S2[2 * i + 17], eg2)); o3 = fma2q(qb.y, S2[2 * i + 17], o3);
        }
        float2 w0 = unpack2q(o0), w1 = unpack2q(o1), w2 = unpack2q(o2), w3 = unpack2q(o3);
        float o = ((w0.x + w0.y) + (w1.x + w1.y)) + ((w2.x + w2.y) + (w3.x + w3.y));

        float sg = gcur / (1.f + expf(-gcur));
        op[(size_t)t * NDIM2] = o * sg;

        vcur = vnx; gcur = gnx;
        __syncthreads();
    }
}

// ---------------------------------------------------------------------------
extern "C" void kernel_launch(void* const* d_in, const int* in_sizes, int n_in,
                              void* d_out, int out_size) {
    const float* H    = (const float*)d_in[0];
    const float* Win  = (const float*)d_in[1];
    const float* qw   = (const float*)d_in[2];
    const float* kw   = (const float*)d_in[3];
    const float* vw   = (const float*)d_in[4];
    const float* dtb  = (const float*)d_in[5];
    const float* Alog = (const float*)d_in[6];
    const float* Wg   = (const float*)d_in[7];
    float* out = (float*)d_out;

    void *p_wtin = nullptr, *p_wtg = nullptr, *p_qkvba = nullptr, *p_gate = nullptr, *p_a = nullptr;
    cudaGetSymbolAddress(&p_wtin,  g_wt_in);
    cudaGetSymbolAddress(&p_wtg,   g_wt_gate);
    cudaGetSymbolAddress(&p_qkvba, g_qkvba);
    cudaGetSymbolAddress(&p_gate,  g_gate);
    cudaGetSymbolAddress(&p_a,     g_a32);
    cudaFuncSetAttribute(gemm_mma, cudaFuncAttributeMaxDynamicSharedMemorySize, GM_SMEM);

    around_kernel<<<MM, 256>>>(H);
    transpose_kernel<<<dim3(KK / 32, N1PAD / 32), 256>>>(Win, (float*)p_wtin, NDIM1);
    transpose_kernel<<<dim3(KK / 32, NDIM2 / 32), 256>>>(Wg, (float*)p_wtg, NDIM2);

    gemm_mma<<<dim3(N1PAD / 128, MM / 128), 256, GM_SMEM>>>(
        (const float*)p_a, (const float*)p_wtin, (float*)p_qkvba, NDIM1);
    gemm_mma<<<dim3(NDIM2 / 128, MM / 128), 256, GM_SMEM>>>(
        (const float*)p_a, (const float*)p_wtg, (float*)p_gate, NDIM2);

    prep_kernel<<<MM, 256>>>(qw, kw, vw, dtb, Alog);
    scan_kernel<<<BB * NH, 128>>>(out);
}

// round 7
// speedup vs baseline: 1.6340x; 1.0499x over previous
#include <cuda_runtime.h>
#include <math.h>
#include <cstdint>

// ---------------------------------------------------------------------------
// Problem constants
// ---------------------------------------------------------------------------
#define BB 4
#define TT 4096
#define NH 16
#define DH 64
#define HV 128
#define NDIM1 4128            // 2*KEY_DIM + VALUE_DIM + 2*N_HEADS
#define NDIM2 2048            // N_HEADS * HEAD_V
#define MM (BB*TT)            // 16384
#define KK 1024
#define N1PAD 4224            // 33 * 128 (W_in cols padded)
#define NTOT (N1PAD + NDIM2)  // 6272 combined weight cols

#define GM_SMEM 81920         // 2 buffers x (A 20480 + B 20480), stride-40 rows

// ---------------------------------------------------------------------------
// Scratch (no cudaMalloc allowed)
// ---------------------------------------------------------------------------
__device__ float g_qkvba[(size_t)MM * NDIM1];
__device__ float g_gate [(size_t)MM * NDIM2];
__device__ float g_q [(size_t)BB*NH*TT*DH];
__device__ float g_k [(size_t)BB*NH*TT*DH];
__device__ float g_v [(size_t)BB*NH*TT*HV];
__device__ float g_eg[(size_t)BB*NH*TT];
__device__ float g_be[(size_t)BB*NH*TT];
__device__ float g_a32[(size_t)MM * KK];        // tf32-rounded, k-permuted A
__device__ float g_wt [(size_t)NTOT * KK];      // combined W_in^T | W_gate^T (tf32, k-permuted)

// ---------------------------------------------------------------------------
// Helpers
// ---------------------------------------------------------------------------
__device__ __forceinline__ uint32_t smem_u32(const void* p) {
    uint32_t a;
    asm("{ .reg .u64 t; cvta.to.shared.u64 t, %1; cvt.u32.u64 %0, t; }" : "=r"(a) : "l"(p));
    return a;
}
// cvt.rna.tf32.f32 requires a .b32 destination register
__device__ __forceinline__ float to_tf32(float x) {
    uint32_t r; asm("cvt.rna.tf32.f32 %0, %1;" : "=r"(r) : "f"(x));
    return __uint_as_float(r);
}
// within-8 k permutation: pair (c, c+4) becomes adjacent
__device__ __forceinline__ int kperm(int c) {
    return (c & ~7) | ((c & 3) << 1) | ((c >> 2) & 1);
}
__device__ __forceinline__ void cpa16(uint32_t dst, const void* src) {
    asm volatile("cp.async.cg.shared.global [%0], [%1], 16;" :: "r"(dst), "l"(src) : "memory");
}
__device__ __forceinline__ void cpa_commit() {
    asm volatile("cp.async.commit_group;" ::: "memory");
}

// tf32 mma m16n8k8, row.col, f32 accum (base ISA, sm_80+)
__device__ __forceinline__ void mma_tf32(float* d, const uint32_t* a, const uint32_t* b) {
    asm volatile(
        "mma.sync.aligned.m16n8k8.row.col.f32.tf32.tf32.f32 "
        "{%0,%1,%2,%3}, {%4,%5,%6,%7}, {%8,%9}, {%0,%1,%2,%3};"
        : "+f"(d[0]), "+f"(d[1]), "+f"(d[2]), "+f"(d[3])
        : "r"(a[0]), "r"(a[1]), "r"(a[2]), "r"(a[3]), "r"(b[0]), "r"(b[1]));
}

// f32x2 packed math
typedef unsigned long long ull;
__device__ __forceinline__ ull fma2q(ull a, ull b, ull c) {
    ull d; asm("fma.rn.f32x2 %0, %1, %2, %3;" : "=l"(d) : "l"(a), "l"(b), "l"(c)); return d;
}
__device__ __forceinline__ ull mul2q(ull a, ull b) {
    ull d; asm("mul.rn.f32x2 %0, %1, %2;" : "=l"(d) : "l"(a), "l"(b)); return d;
}
__device__ __forceinline__ ull pack2q(float a, float b) {
    ull r; asm("mov.b64 %0, {%1, %2};" : "=l"(r) : "f"(a), "f"(b)); return r;
}
__device__ __forceinline__ float2 unpack2q(ull v) {
    float2 r; asm("mov.b64 {%0, %1}, %2;" : "=f"(r.x), "=f"(r.y) : "l"(v)); return r;
}

// ---------------------------------------------------------------------------
// A pre-pass: tf32 round + k-permute
// ---------------------------------------------------------------------------
__global__ void __launch_bounds__(256) around_kernel(const float* __restrict__ H) {
    size_t row = blockIdx.x;
    const float* src = H + row * KK;
    float* dst = g_a32 + row * KK;
#pragma unroll
    for (int r = 0; r < 4; r++) {
        int c = threadIdx.x + r * 256;
        dst[kperm(c)] = to_tf32(src[c]);
    }
}

// ---------------------------------------------------------------------------
// Weight transpose: Wt[n][kperm(k)] = tf32(W[k][n]), zero-padded rows
// ---------------------------------------------------------------------------
__global__ void __launch_bounds__(256) transpose_kernel(const float* __restrict__ W,
                                                        float* __restrict__ Wt, int N) {
    __shared__ float tile[32][33];
    int k0 = blockIdx.x * 32, n0 = blockIdx.y * 32;
    int tx = threadIdx.x & 31, ty = threadIdx.x >> 5;   // 32 x 8
#pragma unroll
    for (int i = 0; i < 32; i += 8) {
        int n = n0 + tx;
        float v = (n < N) ? W[(size_t)(k0 + ty + i) * N + n] : 0.f;
        tile[ty + i][tx] = to_tf32(v);
    }
    __syncthreads();
#pragma unroll
    for (int i = 0; i < 32; i += 8)
        Wt[(size_t)(n0 + ty + i) * KK + kperm(k0 + tx)] = tile[tx][ty + i];
}

// ---------------------------------------------------------------------------
// Fused tf32 mma.sync GEMM over combined weights:
//   cols [0, 4128)       -> g_qkvba
//   cols [4224, 6272)    -> g_gate (shifted by 4224)
// CTA 128x128, K-chunk 32, cp.async double buffer, 8 warps (32x64 each)
// Smem rows stride 40 floats (160B): bank = 8*gid + 2*tig -> conflict-free LDS.64
// ---------------------------------------------------------------------------
__global__ void __launch_bounds__(256) gemm_mma(const float* __restrict__ A,
                                                const float* __restrict__ Bt,
                                                float* __restrict__ C1,
                                                float* __restrict__ C2) {
    extern __shared__ float smf[];                 // [2][A:128x40 | B:128x40]
    uint32_t sbase = smem_u32(smf);

    int tid = threadIdx.x;
    int lane = tid & 31, wid = tid >> 5;
    int gid = lane >> 2, tig = lane & 3;
    int wm = wid & 3, wn = wid >> 2;               // 4 x 2 warp grid
    int m0 = blockIdx.y * 128;
    int n0 = blockIdx.x * 128;

    float acc[2][8][4];
#pragma unroll
    for (int mt = 0; mt < 2; mt++)
#pragma unroll
        for (int nt = 0; nt < 8; nt++)
#pragma unroll
            for (int i = 0; i < 4; i++) acc[mt][nt][i] = 0.f;

    const float* aBase = A  + (size_t)m0 * KK;
    const float* bBase = Bt + (size_t)n0 * KK;

    auto load_tile = [&](int ch, int b) {
        uint32_t a_dst = sbase + b * 40960u;
        uint32_t b_dst = a_dst + 20480u;
        const float* aS = aBase + ch * 32;
        const float* bS = bBase + ch * 32;
#pragma unroll
        for (int i = 0; i < 4; i++) {
            int id = tid + 256 * i;
            int row = id >> 3, seg = id & 7;
            cpa16(a_dst + row * 160u + seg * 16u, aS + (size_t)row * KK + seg * 4);
            cpa16(b_dst + row * 160u + seg * 16u, bS + (size_t)row * KK + seg * 4);
        }
        cpa_commit();
    };

    load_tile(0, 0);
    for (int ch = 0; ch < KK / 32; ch++) {
        if (ch + 1 < KK / 32) {
            load_tile(ch + 1, (ch + 1) & 1);
            asm volatile("cp.async.wait_group 1;" ::: "memory");
        } else {
            asm volatile("cp.async.wait_group 0;" ::: "memory");
        }
        __syncthreads();

        const float* As_f = smf + (ch & 1) * 10240;
        const float* Bs_f = As_f + 5120;
        const float* aW = As_f + (wm * 32 + gid) * 40 + 2 * tig;
        const float* bW = Bs_f + (wn * 64 + gid) * 40 + 2 * tig;

#pragma unroll
        for (int ks = 0; ks < 4; ks++) {
            uint32_t af[2][4];
#pragma unroll
            for (int mt = 0; mt < 2; mt++) {
                float2 v0 = *(const float2*)(aW + (mt * 16) * 40 + ks * 8);
                float2 v1 = *(const float2*)(aW + (mt * 16 + 8) * 40 + ks * 8);
                af[mt][0] = __float_as_uint(v0.x);
                af[mt][2] = __float_as_uint(v0.y);
                af[mt][1] = __float_as_uint(v1.x);
                af[mt][3] = __float_as_uint(v1.y);
            }
            uint32_t bf[8][2];
#pragma unroll
            for (int nt = 0; nt < 8; nt++) {
                float2 v = *(const float2*)(bW + (nt * 8) * 40 + ks * 8);
                bf[nt][0] = __float_as_uint(v.x);
                bf[nt][1] = __float_as_uint(v.y);
            }
#pragma unroll
            for (int mt = 0; mt < 2; mt++)
#pragma unroll
                for (int nt = 0; nt < 8; nt++)
                    mma_tf32(acc[mt][nt], af[mt], bf[nt]);
        }
        __syncthreads();
    }

    // routed epilogue
#pragma unroll
    for (int mt = 0; mt < 2; mt++) {
        int row = m0 + wm * 32 + mt * 16 + gid;
#pragma unroll
        for (int nt = 0; nt < 8; nt++) {
            int col = n0 + wn * 64 + nt * 8 + 2 * tig;
            float2 lo = make_float2(acc[mt][nt][0], acc[mt][nt][1]);
            float2 hi = make_float2(acc[mt][nt][2], acc[mt][nt][3]);
            if (col < NDIM1) {
                *(float2*)&C1[(size_t)row * NDIM1 + col] = lo;
                *(float2*)&C1[(size_t)(row + 8) * NDIM1 + col] = hi;
            } else if (col >= N1PAD) {
                int c2 = col - N1PAD;
                *(float2*)&C2[(size_t)row * NDIM2 + c2] = lo;
                *(float2*)&C2[(size_t)(row + 8) * NDIM2 + c2] = hi;
            }
        }
    }
}

// ---------------------------------------------------------------------------
// Prep: causal conv4 + SiLU on q/k/v, l2norm on q/k, beta/exp(g)
// ---------------------------------------------------------------------------
__device__ __forceinline__ float silu_f(float y) { return y / (1.f + expf(-y)); }

__global__ void __launch_bounds__(256) prep_kernel(const float* __restrict__ qw,
                                                   const float* __restrict__ kw,
                                                   const float* __restrict__ vw,
                                                   const float* __restrict__ dtb,
                                                   const float* __restrict__ Alog) {
    __shared__ float sq[1024];
    __shared__ float sk[1024];
    __shared__ float sscale[32];
    int row = blockIdx.x;
    int b = row / TT, t = row % TT;
    int tid = threadIdx.x;
    const float* base = g_qkvba + (size_t)row * NDIM1;

#pragma unroll
    for (int r = 0; r < 4; r++) {
        int c = tid + r * 256;
        float yq = 0.f, yk = 0.f;
#pragma unroll
        for (int i = 0; i < 4; i++) {
            int tt = t - 3 + i;
            if (tt >= 0) {
                const float* xr = base + (size_t)(i - 3) * NDIM1;
                yq = fmaf(xr[c], qw[c * 4 + i], yq);
                yk = fmaf(xr[1024 + c], kw[c * 4 + i], yk);
            }
        }
        sq[c] = silu_f(yq);
        sk[c] = silu_f(yk);
    }
#pragma unroll
    for (int r = 0; r < 8; r++) {
        int cv = tid + r * 256;
        float yv = 0.f;
#pragma unroll
        for (int i = 0; i < 4; i++) {
            int tt = t - 3 + i;
            if (tt >= 0)
                yv = fmaf(base[(size_t)(i - 3) * NDIM1 + 2048 + cv], vw[cv * 4 + i], yv);
        }
        int h = cv >> 7, j = cv & 127;
        g_v[(((size_t)(b * NH + h)) * TT + t) * HV + j] = silu_f(yv);
    }
    __syncthreads();
    if (tid < 16) {
        float s = 0.f;
#pragma unroll
        for (int d = 0; d < 64; d++) { float x = sq[tid * 64 + d]; s = fmaf(x, x, s); }
        sscale[tid] = rsqrtf(s + 1e-6f) * 0.125f;
    } else if (tid < 32) {
        int h = tid - 16;
        float s = 0.f;
#pragma unroll
        for (int d = 0; d < 64; d++) { float x = sk[h * 64 + d]; s = fmaf(x, x, s); }
        sscale[tid] = rsqrtf(s + 1e-6f);
    }
    if (tid < 16) {
        int h = tid;
        float bp = base[4096 + h];
        float ap = base[4112 + h];
        float beta = 1.f / (1.f + expf(-bp));
        float x = ap + dtb[h];
        float sp = (x > 20.f) ? x : log1pf(expf(x));
        float g = -expf(Alog[h]) * sp;
        size_t idx = (size_t)(b * NH + h) * TT + t;
        g_eg[idx] = expf(g);
        g_be[idx] = beta;
    }
    __syncthreads();
#pragma unroll
    for (int r = 0; r < 4; r++) {
        int c = tid + r * 256;
        int h = c >> 6, d = c & 63;
        size_t idx = (((size_t)(b * NH + h)) * TT + t) * DH + d;
        g_q[idx] = sq[c] * sscale[h];
        g_k[idx] = sk[c] * sscale[16 + h];
    }
}

// ---------------------------------------------------------------------------
// Scan: one block per (b,h), 128 threads, thread j owns S[:,j]; f32x2 math
// ---------------------------------------------------------------------------
__global__ void __launch_bounds__(128) scan_kernel(float* __restrict__ out) {
    __shared__ __align__(16) float skb[2][64];
    __shared__ __align__(16) float sqb[2][64];
    __shared__ float seg[2], sbe[2];
    int bh = blockIdx.x;
    int b = bh >> 4, h = bh & 15;
    int j = threadIdx.x;
    const float* qp  = g_q  + (size_t)bh * TT * DH;
    const float* kp  = g_k  + (size_t)bh * TT * DH;
    const float* vp  = g_v  + (size_t)bh * TT * HV + j;
    const float* egp = g_eg + (size_t)bh * TT;
    const float* bep = g_be + (size_t)bh * TT;
    const float* gp  = g_gate + (size_t)b * TT * NDIM2 + h * HV + j;
    float* op        = out    + (size_t)b * TT * NDIM2 + h * HV + j;

    ull S2[32];
#pragma unroll
    for (int d = 0; d < 32; d++) S2[d] = 0ULL;

    if (j < 64) skb[0][j] = kp[j]; else sqb[0][j - 64] = qp[j - 64];
    if (j == 0) { seg[0] = egp[0]; sbe[0] = bep[0]; }
    __syncthreads();
    float vcur = vp[0];
    float gcur = gp[0];

    for (int t = 0; t < TT; t++) {
        int cur = t & 1, nxt = cur ^ 1;
        if (t + 1 < TT) {
            if (j < 64) skb[nxt][j] = kp[(size_t)(t + 1) * 64 + j];
            else        sqb[nxt][j - 64] = qp[(size_t)(t + 1) * 64 + (j - 64)];
            if (j == 0) { seg[nxt] = egp[t + 1]; sbe[nxt] = bep[t + 1]; }
        }
        float vnx = (t + 1 < TT) ? vp[(size_t)(t + 1) * HV] : 0.f;
        float gnx = (t + 1 < TT) ? gp[(size_t)(t + 1) * NDIM2] : 0.f;

        float eg = seg[cur], be = sbe[cur];
        const ulonglong2* k2p = (const ulonglong2*)skb[cur];
        const ulonglong2* q2p = (const ulonglong2*)sqb[cur];

        ull a0 = 0, a1 = 0, a2 = 0, a3 = 0;
#pragma unroll
        for (int i = 0; i < 8; i++) {
            ulonglong2 ka = k2p[i];
            ulonglong2 kb = k2p[i + 8];
            a0 = fma2q(ka.x, S2[2 * i],      a0);
            a1 = fma2q(ka.y, S2[2 * i + 1],  a1);
            a2 = fma2q(kb.x, S2[2 * i + 16], a2);
            a3 = fma2q(kb.y, S2[2 * i + 17], a3);
        }
        float2 u0 = unpack2q(a0), u1 = unpack2q(a1), u2 = unpack2q(a2), u3 = unpack2q(a3);
        float kS = ((u0.x + u0.y) + (u1.x + u1.y)) + ((u2.x + u2.y) + (u3.x + u3.y));
        float vnew = (vcur - eg * kS) * be;

        ull eg2 = pack2q(eg, eg);
        ull vn2 = pack2q(vnew, vnew);
        ull o0 = 0, o1 = 0, o2 = 0, o3 = 0;
#pragma unroll
        for (int i = 0; i < 8; i++) {
            ulonglong2 ka = k2p[i],  kb = k2p[i + 8];
            ulonglong2 qa = q2p[i],  qb = q2p[i + 8];
            S2[2 * i]      = fma2q(ka.x, vn2, mul2q(S2[2 * i],      eg2)); o0 = fma2q(qa.x, S2[2 * i],      o0);
            S2[2 * i + 1]  = fma2q(ka.y, vn2, mul2q(S2[2 * i + 1],  eg2)); o1 = fma2q(qa.y, S2[2 * i + 1],  o1);
            S2[2 * i + 16] = fma2q(kb.x, vn2, mul2q(S2[2 * i + 16], eg2)); o2 = fma2q(qb.x, S2[2 * i + 16], o2);
            S2[2 * i + 17] = fma2q(kb.y, vn2, mul2q(S2[2 * i + 17], eg2)); o3 = fma2q(qb.y, S2[2 * i + 17], o3);
        }
        float2 w0 = unpack2q(o0), w1 = unpack2q(o1), w2 = unpack2q(o2), w3 = unpack2q(o3);
        float o = ((w0.x + w0.y) + (w1.x + w1.y)) + ((w2.x + w2.y) + (w3.x + w3.y));

        float sg = gcur / (1.f + expf(-gcur));
        op[(size_t)t * NDIM2] = o * sg;

        vcur = vnx; gcur = gnx;
        __syncthreads();
    }
}

// ---------------------------------------------------------------------------
extern "C" void kernel_launch(void* const* d_in, const int* in_sizes, int n_in,
                              void* d_out, int out_size) {
    const float* H    = (const float*)d_in[0];
    const float* Win  = (const float*)d_in[1];
    const float* qw   = (const float*)d_in[2];
    const float* kw   = (const float*)d_in[3];
    const float* vw   = (const float*)d_in[4];
    const float* dtb  = (const float*)d_in[5];
    const float* Alog = (const float*)d_in[6];
    const float* Wg   = (const float*)d_in[7];
    float* out = (float*)d_out;

    void *p_wt = nullptr, *p_qkvba = nullptr, *p_gate = nullptr, *p_a = nullptr;
    cudaGetSymbolAddress(&p_wt,    g_wt);
    cudaGetSymbolAddress(&p_qkvba, g_qkvba);
    cudaGetSymbolAddress(&p_gate,  g_gate);
    cudaGetSymbolAddress(&p_a,     g_a32);
    cudaFuncSetAttribute(gemm_mma, cudaFuncAttributeMaxDynamicSharedMemorySize, GM_SMEM);

    around_kernel<<<MM, 256>>>(H);
    transpose_kernel<<<dim3(KK / 32, N1PAD / 32), 256>>>(Win, (float*)p_wt, NDIM1);
    transpose_kernel<<<dim3(KK / 32, NDIM2 / 32), 256>>>(
        Wg, (float*)p_wt + (size_t)N1PAD * KK, NDIM2);

    gemm_mma<<<dim3(NTOT / 128, MM / 128), 256, GM_SMEM>>>(
        (const float*)p_a, (const float*)p_wt, (float*)p_qkvba, (float*)p_gate);

    prep_kernel<<<MM, 256>>>(qw, kw, vw, dtb, Alog);
    scan_kernel<<<BB * NH, 128>>>(out);
}

// round 8
// speedup vs baseline: 3.2431x; 1.9847x over previous
#include <cuda_runtime.h>
#include <math.h>
#include <cstdint>

// ---------------------------------------------------------------------------
// Problem constants
// ---------------------------------------------------------------------------
#define BB 4
#define TT 4096
#define NH 16
#define DH 64
#define HV 128
#define NDIM1 4128            // 2*KEY_DIM + VALUE_DIM + 2*N_HEADS
#define NDIM2 2048            // N_HEADS * HEAD_V
#define MM (BB*TT)            // 16384
#define KK 1024
#define N1PAD 4224            // 33 * 128 (W_in cols padded)
#define NTOT (N1PAD + NDIM2)  // 6272 combined weight cols

#define GM_SMEM 81920         // 2 buffers x (A 20480 + B 20480), stride-40 rows

// ---------------------------------------------------------------------------
// Scratch (no cudaMalloc allowed)
// ---------------------------------------------------------------------------
__device__ float g_qkvba[(size_t)MM * NDIM1];
__device__ float g_gate [(size_t)MM * NDIM2];
__device__ float g_q [(size_t)BB*NH*TT*DH];
__device__ float g_k [(size_t)BB*NH*TT*DH];
__device__ float g_v [(size_t)BB*NH*TT*HV];
__device__ float g_eg[(size_t)BB*NH*TT];
__device__ float g_be[(size_t)BB*NH*TT];
__device__ float g_a32[(size_t)MM * KK];        // tf32-rounded, k-permuted A
__device__ float g_wt [(size_t)NTOT * KK];      // combined W_in^T | W_gate^T (tf32, k-permuted)

// ---------------------------------------------------------------------------
// Helpers
// ---------------------------------------------------------------------------
__device__ __forceinline__ uint32_t smem_u32(const void* p) {
    uint32_t a;
    asm("{ .reg .u64 t; cvta.to.shared.u64 t, %1; cvt.u32.u64 %0, t; }" : "=r"(a) : "l"(p));
    return a;
}
__device__ __forceinline__ float to_tf32(float x) {
    uint32_t r; asm("cvt.rna.tf32.f32 %0, %1;" : "=r"(r) : "f"(x));
    return __uint_as_float(r);
}
__device__ __forceinline__ int kperm(int c) {
    return (c & ~7) | ((c & 3) << 1) | ((c >> 2) & 1);
}
__device__ __forceinline__ void cpa16(uint32_t dst, const void* src) {
    asm volatile("cp.async.cg.shared.global [%0], [%1], 16;" :: "r"(dst), "l"(src) : "memory");
}
__device__ __forceinline__ void cpa4(uint32_t dst, const void* src) {
    asm volatile("cp.async.ca.shared.global [%0], [%1], 4;" :: "r"(dst), "l"(src) : "memory");
}
__device__ __forceinline__ void cpa_commit() {
    asm volatile("cp.async.commit_group;" ::: "memory");
}
__device__ __forceinline__ void cpa_wait0() {
    asm volatile("cp.async.wait_group 0;" ::: "memory");
}

// tf32 mma m16n8k8, row.col, f32 accum (base ISA, sm_80+)
__device__ __forceinline__ void mma_tf32(float* d, const uint32_t* a, const uint32_t* b) {
    asm volatile(
        "mma.sync.aligned.m16n8k8.row.col.f32.tf32.tf32.f32 "
        "{%0,%1,%2,%3}, {%4,%5,%6,%7}, {%8,%9}, {%0,%1,%2,%3};"
        : "+f"(d[0]), "+f"(d[1]), "+f"(d[2]), "+f"(d[3])
        : "r"(a[0]), "r"(a[1]), "r"(a[2]), "r"(a[3]), "r"(b[0]), "r"(b[1]));
}

// f32x2 packed math
typedef unsigned long long ull;
__device__ __forceinline__ ull fma2q(ull a, ull b, ull c) {
    ull d; asm("fma.rn.f32x2 %0, %1, %2, %3;" : "=l"(d) : "l"(a), "l"(b), "l"(c)); return d;
}
__device__ __forceinline__ ull mul2q(ull a, ull b) {
    ull d; asm("mul.rn.f32x2 %0, %1, %2;" : "=l"(d) : "l"(a), "l"(b)); return d;
}
__device__ __forceinline__ ull pack2q(float a, float b) {
    ull r; asm("mov.b64 %0, {%1, %2};" : "=l"(r) : "f"(a), "f"(b)); return r;
}
__device__ __forceinline__ float2 unpack2q(ull v) {
    float2 r; asm("mov.b64 {%0, %1}, %2;" : "=f"(r.x), "=f"(r.y) : "l"(v)); return r;
}

// ---------------------------------------------------------------------------
// A pre-pass: tf32 round + k-permute
// ---------------------------------------------------------------------------
__global__ void __launch_bounds__(256) around_kernel(const float* __restrict__ H) {
    size_t row = blockIdx.x;
    const float* src = H + row * KK;
    float* dst = g_a32 + row * KK;
#pragma unroll
    for (int r = 0; r < 4; r++) {
        int c = threadIdx.x + r * 256;
        dst[kperm(c)] = to_tf32(src[c]);
    }
}

// ---------------------------------------------------------------------------
// Weight transpose: Wt[n][kperm(k)] = tf32(W[k][n]), zero-padded rows
// ---------------------------------------------------------------------------
__global__ void __launch_bounds__(256) transpose_kernel(const float* __restrict__ W,
                                                        float* __restrict__ Wt, int N) {
    __shared__ float tile[32][33];
    int k0 = blockIdx.x * 32, n0 = blockIdx.y * 32;
    int tx = threadIdx.x & 31, ty = threadIdx.x >> 5;   // 32 x 8
#pragma unroll
    for (int i = 0; i < 32; i += 8) {
        int n = n0 + tx;
        float v = (n < N) ? W[(size_t)(k0 + ty + i) * N + n] : 0.f;
        tile[ty + i][tx] = to_tf32(v);
    }
    __syncthreads();
#pragma unroll
    for (int i = 0; i < 32; i += 8)
        Wt[(size_t)(n0 + ty + i) * KK + kperm(k0 + tx)] = tile[tx][ty + i];
}

// ---------------------------------------------------------------------------
// Fused tf32 mma.sync GEMM (cols [0,4128)->qkvba, [4224,6272)->gate)
// ---------------------------------------------------------------------------
__global__ void __launch_bounds__(256) gemm_mma(const float* __restrict__ A,
                                                const float* __restrict__ Bt,
                                                float* __restrict__ C1,
                                                float* __restrict__ C2) {
    extern __shared__ float smf[];                 // [2][A:128x40 | B:128x40]
    uint32_t sbase = smem_u32(smf);

    int tid = threadIdx.x;
    int lane = tid & 31, wid = tid >> 5;
    int gid = lane >> 2, tig = lane & 3;
    int wm = wid & 3, wn = wid >> 2;               // 4 x 2 warp grid
    int m0 = blockIdx.y * 128;
    int n0 = blockIdx.x * 128;

    float acc[2][8][4];
#pragma unroll
    for (int mt = 0; mt < 2; mt++)
#pragma unroll
        for (int nt = 0; nt < 8; nt++)
#pragma unroll
            for (int i = 0; i < 4; i++) acc[mt][nt][i] = 0.f;

    const float* aBase = A  + (size_t)m0 * KK;
    const float* bBase = Bt + (size_t)n0 * KK;

    auto load_tile = [&](int ch, int b) {
        uint32_t a_dst = sbase + b * 40960u;
        uint32_t b_dst = a_dst + 20480u;
        const float* aS = aBase + ch * 32;
        const float* bS = bBase + ch * 32;
#pragma unroll
        for (int i = 0; i < 4; i++) {
            int id = tid + 256 * i;
            int row = id >> 3, seg = id & 7;
            cpa16(a_dst + row * 160u + seg * 16u, aS + (size_t)row * KK + seg * 4);
            cpa16(b_dst + row * 160u + seg * 16u, bS + (size_t)row * KK + seg * 4);
        }
        cpa_commit();
    };

    load_tile(0, 0);
    for (int ch = 0; ch < KK / 32; ch++) {
        if (ch + 1 < KK / 32) {
            load_tile(ch + 1, (ch + 1) & 1);
            asm volatile("cp.async.wait_group 1;" ::: "memory");
        } else {
            asm volatile("cp.async.wait_group 0;" ::: "memory");
        }
        __syncthreads();

        const float* As_f = smf + (ch & 1) * 10240;
        const float* Bs_f = As_f + 5120;
        const float* aW = As_f + (wm * 32 + gid) * 40 + 2 * tig;
        const float* bW = Bs_f + (wn * 64 + gid) * 40 + 2 * tig;

#pragma unroll
        for (int ks = 0; ks < 4; ks++) {
            uint32_t af[2][4];
#pragma unroll
            for (int mt = 0; mt < 2; mt++) {
                float2 v0 = *(const float2*)(aW + (mt * 16) * 40 + ks * 8);
                float2 v1 = *(const float2*)(aW + (mt * 16 + 8) * 40 + ks * 8);
                af[mt][0] = __float_as_uint(v0.x);
                af[mt][2] = __float_as_uint(v0.y);
                af[mt][1] = __float_as_uint(v1.x);
                af[mt][3] = __float_as_uint(v1.y);
            }
            uint32_t bf[8][2];
#pragma unroll
            for (int nt = 0; nt < 8; nt++) {
                float2 v = *(const float2*)(bW + (nt * 8) * 40 + ks * 8);
                bf[nt][0] = __float_as_uint(v.x);
                bf[nt][1] = __float_as_uint(v.y);
            }
#pragma unroll
            for (int mt = 0; mt < 2; mt++)
#pragma unroll
                for (int nt = 0; nt < 8; nt++)
                    mma_tf32(acc[mt][nt], af[mt], bf[nt]);
        }
        __syncthreads();
    }

    // routed epilogue
#pragma unroll
    for (int mt = 0; mt < 2; mt++) {
        int row = m0 + wm * 32 + mt * 16 + gid;
#pragma unroll
        for (int nt = 0; nt < 8; nt++) {
            int col = n0 + wn * 64 + nt * 8 + 2 * tig;
            float2 lo = make_float2(acc[mt][nt][0], acc[mt][nt][1]);
            float2 hi = make_float2(acc[mt][nt][2], acc[mt][nt][3]);
            if (col < NDIM1) {
                *(float2*)&C1[(size_t)row * NDIM1 + col] = lo;
                *(float2*)&C1[(size_t)(row + 8) * NDIM1 + col] = hi;
            } else if (col >= N1PAD) {
                int c2 = col - N1PAD;
                *(float2*)&C2[(size_t)row * NDIM2 + c2] = lo;
                *(float2*)&C2[(size_t)(row + 8) * NDIM2 + c2] = hi;
            }
        }
    }
}

// ---------------------------------------------------------------------------
// Prep: causal conv4 + SiLU on q/k/v, l2norm on q/k, beta/exp(g)
// ---------------------------------------------------------------------------
__device__ __forceinline__ float silu_f(float y) { return y / (1.f + expf(-y)); }

__global__ void __launch_bounds__(256) prep_kernel(const float* __restrict__ qw,
                                                   const float* __restrict__ kw,
                                                   const float* __restrict__ vw,
                                                   const float* __restrict__ dtb,
                                                   const float* __restrict__ Alog) {
    __shared__ float sq[1024];
    __shared__ float sk[1024];
    __shared__ float sscale[32];
    int row = blockIdx.x;
    int b = row / TT, t = row % TT;
    int tid = threadIdx.x;
    const float* base = g_qkvba + (size_t)row * NDIM1;

#pragma unroll
    for (int r = 0; r < 4; r++) {
        int c = tid + r * 256;
        float yq = 0.f, yk = 0.f;
#pragma unroll
        for (int i = 0; i < 4; i++) {
            int tt = t - 3 + i;
            if (tt >= 0) {
                const float* xr = base + (size_t)(i - 3) * NDIM1;
                yq = fmaf(xr[c], qw[c * 4 + i], yq);
                yk = fmaf(xr[1024 + c], kw[c * 4 + i], yk);
            }
        }
        sq[c] = silu_f(yq);
        sk[c] = silu_f(yk);
    }
#pragma unroll
    for (int r = 0; r < 8; r++) {
        int cv = tid + r * 256;
        float yv = 0.f;
#pragma unroll
        for (int i = 0; i < 4; i++) {
            int tt = t - 3 + i;
            if (tt >= 0)
                yv = fmaf(base[(size_t)(i - 3) * NDIM1 + 2048 + cv], vw[cv * 4 + i], yv);
        }
        int h = cv >> 7, j = cv & 127;
        g_v[(((size_t)(b * NH + h)) * TT + t) * HV + j] = silu_f(yv);
    }
    __syncthreads();
    if (tid < 16) {
        float s = 0.f;
#pragma unroll
        for (int d = 0; d < 64; d++) { float x = sq[tid * 64 + d]; s = fmaf(x, x, s); }
        sscale[tid] = rsqrtf(s + 1e-6f) * 0.125f;
    } else if (tid < 32) {
        int h = tid - 16;
        float s = 0.f;
#pragma unroll
        for (int d = 0; d < 64; d++) { float x = sk[h * 64 + d]; s = fmaf(x, x, s); }
        sscale[tid] = rsqrtf(s + 1e-6f);
    }
    if (tid < 16) {
        int h = tid;
        float bp = base[4096 + h];
        float ap = base[4112 + h];
        float beta = 1.f / (1.f + expf(-bp));
        float x = ap + dtb[h];
        float sp = (x > 20.f) ? x : log1pf(expf(x));
        float g = -expf(Alog[h]) * sp;
        size_t idx = (size_t)(b * NH + h) * TT + t;
        g_eg[idx] = expf(g);
        g_be[idx] = beta;
    }
    __syncthreads();
#pragma unroll
    for (int r = 0; r < 4; r++) {
        int c = tid + r * 256;
        int h = c >> 6, d = c & 63;
        size_t idx = (((size_t)(b * NH + h)) * TT + t) * DH + d;
        g_q[idx] = sq[c] * sscale[h];
        g_k[idx] = sk[c] * sscale[16 + h];
    }
}

// ---------------------------------------------------------------------------
// Scan: one block per (b,h), 128 threads, thread j owns S[:,j]; f32x2 math.
// 8-step tiles, cp.async double-buffered staging of k/q/v/gate/eg/beta:
// DRAM latency hidden behind ~8x260 cyc of compute; one barrier per tile.
// ---------------------------------------------------------------------------
#define ST 8   // scan tile

__global__ void __launch_bounds__(128) scan_kernel(float* __restrict__ out) {
    __shared__ __align__(16) float sk[2][ST][64];
    __shared__ __align__(16) float sq[2][ST][64];
    __shared__ __align__(16) float sv[2][ST][128];
    __shared__ __align__(16) float sg[2][ST][128];
    __shared__ __align__(16) float seb[2][2][ST];   // [buf][0=eg,1=be][tt]

    int bh = blockIdx.x;
    int b = bh >> 4, h = bh & 15;
    int j = threadIdx.x;

    const float* kp  = g_k  + (size_t)bh * TT * DH;
    const float* qp  = g_q  + (size_t)bh * TT * DH;
    const float* vp0 = g_v  + (size_t)bh * TT * HV;
    const float* egp = g_eg + (size_t)bh * TT;
    const float* bep = g_be + (size_t)bh * TT;
    const float* gp0 = g_gate + (size_t)b * TT * NDIM2 + h * HV;
    float* op        = out    + (size_t)b * TT * NDIM2 + h * HV + j;

    uint32_t a_sk = smem_u32(&sk[0][0][0]);
    uint32_t a_sq = smem_u32(&sq[0][0][0]);
    uint32_t a_sv = smem_u32(&sv[0][0][0]);
    uint32_t a_sg = smem_u32(&sg[0][0][0]);
    uint32_t a_se = smem_u32(&seb[0][0][0]);

    // stage tile starting at t0 into buffer buf
    auto issue_tile = [&](int t0, int buf) {
        int row = j >> 4, seg = j & 15;             // k/q: 8 rows x 16 segs(16B)
        cpa16(a_sk + buf * (ST*64*4) + row * 256 + seg * 16,
              kp + (size_t)(t0 + row) * DH + seg * 4);
        cpa16(a_sq + buf * (ST*64*4) + row * 256 + seg * 16,
              qp + (size_t)(t0 + row) * DH + seg * 4);
#pragma unroll
        for (int r = 0; r < 2; r++) {               // v/g: 8 rows x 32 segs
            int s = j + r * 128;
            int vrow = s >> 5, col = (s & 31) * 4;
            cpa16(a_sv + buf * (ST*128*4) + vrow * 512 + col * 4,
                  vp0 + (size_t)(t0 + vrow) * HV + col);
            cpa16(a_sg + buf * (ST*128*4) + vrow * 512 + col * 4,
                  gp0 + (size_t)(t0 + vrow) * NDIM2 + col);
        }
        if (j < ST)            cpa4(a_se + buf * (2*ST*4) + j * 4,          egp + t0 + j);
        else if (j < 2 * ST)   cpa4(a_se + buf * (2*ST*4) + ST*4 + (j-ST)*4, bep + t0 + j - ST);
        cpa_commit();
    };

    ull S2[32];
#pragma unroll
    for (int d = 0; d < 32; d++) S2[d] = 0ULL;

    issue_tile(0, 0);
    cpa_wait0();
    __syncthreads();

    for (int t0 = 0; t0 < TT; t0 += ST) {
        int cur = (t0 >> 3) & 1;
        if (t0 + ST < TT) issue_tile(t0 + ST, cur ^ 1);

#pragma unroll 2
        for (int tt = 0; tt < ST; tt++) {
            float eg = seb[cur][0][tt], be = seb[cur][1][tt];
            float vcur = sv[cur][tt][j];
            float gcur = sg[cur][tt][j];
            const ulonglong2* k2p = (const ulonglong2*)sk[cur][tt];
            const ulonglong2* q2p = (const ulonglong2*)sq[cur][tt];

            // kS = k . S_old
            ull a0 = 0, a1 = 0, a2 = 0, a3 = 0;
#pragma unroll
            for (int i = 0; i < 8; i++) {
                ulonglong2 ka = k2p[i];
                ulonglong2 kb = k2p[i + 8];
                a0 = fma2q(ka.x, S2[2 * i],      a0);
                a1 = fma2q(ka.y, S2[2 * i + 1],  a1);
                a2 = fma2q(kb.x, S2[2 * i + 16], a2);
                a3 = fma2q(kb.y, S2[2 * i + 17], a3);
            }
            float2 u0 = unpack2q(a0), u1 = unpack2q(a1), u2 = unpack2q(a2), u3 = unpack2q(a3);
            float kS = ((u0.x + u0.y) + (u1.x + u1.y)) + ((u2.x + u2.y) + (u3.x + u3.y));
            float vnew = (vcur - eg * kS) * be;

            ull eg2 = pack2q(eg, eg);
            ull vn2 = pack2q(vnew, vnew);
            ull o0 = 0, o1 = 0, o2 = 0, o3 = 0;
#pragma unroll
            for (int i = 0; i < 8; i++) {
                ulonglong2 ka = k2p[i],  kb = k2p[i + 8];
                ulonglong2 qa = q2p[i],  qb = q2p[i + 8];
                S2[2 * i]      = fma2q(ka.x, vn2, mul2q(S2[2 * i],      eg2)); o0 = fma2q(qa.x, S2[2 * i],      o0);
                S2[2 * i + 1]  = fma2q(ka.y, vn2, mul2q(S2[2 * i + 1],  eg2)); o1 = fma2q(qa.y, S2[2 * i + 1],  o1);
                S2[2 * i + 16] = fma2q(kb.x, vn2, mul2q(S2[2 * i + 16], eg2)); o2 = fma2q(qb.x, S2[2 * i + 16], o2);
                S2[2 * i + 17] = fma2q(kb.y, vn2, mul2q(S2[2 * i + 17], eg2)); o3 = fma2q(qb.y, S2[2 * i + 17], o3);
            }
            float2 w0 = unpack2q(o0), w1 = unpack2q(o1), w2 = unpack2q(o2), w3 = unpack2q(o3);
            float o = ((w0.x + w0.y) + (w1.x + w1.y)) + ((w2.x + w2.y) + (w3.x + w3.y));

            float sgate = gcur / (1.f + expf(-gcur));
            op[(size_t)(t0 + tt) * NDIM2] = o * sgate;
        }

        if (t0 + ST < TT) cpa_wait0();
        __syncthreads();
    }
}

// ---------------------------------------------------------------------------
extern "C" void kernel_launch(void* const* d_in, const int* in_sizes, int n_in,
                              void* d_out, int out_size) {
    const float* H    = (const float*)d_in[0];
    const float* Win  = (const float*)d_in[1];
    const float* qw   = (const float*)d_in[2];
    const float* kw   = (const float*)d_in[3];
    const float* vw   = (const float*)d_in[4];
    const float* dtb  = (const float*)d_in[5];
    const float* Alog = (const float*)d_in[6];
    const float* Wg   = (const float*)d_in[7];
    float* out = (float*)d_out;

    void *p_wt = nullptr, *p_qkvba = nullptr, *p_gate = nullptr, *p_a = nullptr;
    cudaGetSymbolAddress(&p_wt,    g_wt);
    cudaGetSymbolAddress(&p_qkvba, g_qkvba);
    cudaGetSymbolAddress(&p_gate,  g_gate);
    cudaGetSymbolAddress(&p_a,     g_a32);
    cudaFuncSetAttribute(gemm_mma, cudaFuncAttributeMaxDynamicSharedMemorySize, GM_SMEM);

    around_kernel<<<MM, 256>>>(H);
    transpose_kernel<<<dim3(KK / 32, N1PAD / 32), 256>>>(Win, (float*)p_wt, NDIM1);
    transpose_kernel<<<dim3(KK / 32, NDIM2 / 32), 256>>>(
        Wg, (float*)p_wt + (size_t)N1PAD * KK, NDIM2);

    gemm_mma<<<dim3(NTOT / 128, MM / 128), 256, GM_SMEM>>>(
        (const float*)p_a, (const float*)p_wt, (float*)p_qkvba, (float*)p_gate);

    prep_kernel<<<MM, 256>>>(qw, kw, vw, dtb, Alog);
    scan_kernel<<<BB * NH, 128>>>(out);
}

// round 9
// speedup vs baseline: 4.2650x; 1.3151x over previous
#include <cuda_runtime.h>
#include <cuda_fp16.h>
#include <math.h>
#include <cstdint>

// ---------------------------------------------------------------------------
// Problem constants
// ---------------------------------------------------------------------------
#define BB 4
#define TT 4096
#define NH 16
#define DH 64
#define HV 128
#define NDIM1 4128            // 2*KEY_DIM + VALUE_DIM + 2*N_HEADS
#define NDIM2 2048            // N_HEADS * HEAD_V
#define MM (BB*TT)            // 16384
#define KK 1024
#define N1PAD 4224            // 33 * 128 (W_in cols padded)
#define NTOT (N1PAD + NDIM2)  // 6272 combined weight cols

#define GM_SMEM 81920         // 2 buffers x (A 20480B + B 20480B), 160B rows

// ---------------------------------------------------------------------------
// Scratch (no cudaMalloc allowed)
// ---------------------------------------------------------------------------
__device__ float g_qkvba[(size_t)MM * NDIM1];
__device__ float g_gate [(size_t)MM * NDIM2];
__device__ float g_q [(size_t)BB*NH*TT*DH];
__device__ float g_k [(size_t)BB*NH*TT*DH];
__device__ float g_v [(size_t)BB*NH*TT*HV];
__device__ float g_eg[(size_t)BB*NH*TT];
__device__ float g_be[(size_t)BB*NH*TT];
__device__ __half g_a16[(size_t)MM * KK];       // fp16, k-permuted A
__device__ __half g_wt16[(size_t)NTOT * KK];    // fp16, k-permuted W_in^T | W_gate^T

// ---------------------------------------------------------------------------
// Helpers
// ---------------------------------------------------------------------------
__device__ __forceinline__ uint32_t smem_u32(const void* p) {
    uint32_t a;
    asm("{ .reg .u64 t; cvta.to.shared.u64 t, %1; cvt.u32.u64 %0, t; }" : "=r"(a) : "l"(p));
    return a;
}
// fp16 k-permutation within each 16-group: [0,1,8,9,2,3,10,11,4,5,12,13,6,7,14,15]
// so a single LDS.64 yields fragment halves {2t,2t+1,2t+8,2t+9}
__device__ __forceinline__ int kperm16(int k) {
    return (k & ~15) | (((k & 7) >> 1) << 2) | (((k >> 3) & 1) << 1) | (k & 1);
}
__device__ __forceinline__ void cpa16(uint32_t dst, const void* src) {
    asm volatile("cp.async.cg.shared.global [%0], [%1], 16;" :: "r"(dst), "l"(src) : "memory");
}
__device__ __forceinline__ void cpa4(uint32_t dst, const void* src) {
    asm volatile("cp.async.ca.shared.global [%0], [%1], 4;" :: "r"(dst), "l"(src) : "memory");
}
__device__ __forceinline__ void cpa_commit() {
    asm volatile("cp.async.commit_group;" ::: "memory");
}
__device__ __forceinline__ void cpa_wait0() {
    asm volatile("cp.async.wait_group 0;" ::: "memory");
}

// fp16 mma m16n8k16, row.col, f32 accum (base ISA, sm_80+)
__device__ __forceinline__ void mma_f16(float* d, const uint32_t* a, const uint32_t* b) {
    asm volatile(
        "mma.sync.aligned.m16n8k16.row.col.f32.f16.f16.f32 "
        "{%0,%1,%2,%3}, {%4,%5,%6,%7}, {%8,%9}, {%0,%1,%2,%3};"
        : "+f"(d[0]), "+f"(d[1]), "+f"(d[2]), "+f"(d[3])
        : "r"(a[0]), "r"(a[1]), "r"(a[2]), "r"(a[3]), "r"(b[0]), "r"(b[1]));
}

// f32x2 packed math
typedef unsigned long long ull;
__device__ __forceinline__ ull fma2q(ull a, ull b, ull c) {
    ull d; asm("fma.rn.f32x2 %0, %1, %2, %3;" : "=l"(d) : "l"(a), "l"(b), "l"(c)); return d;
}
__device__ __forceinline__ ull mul2q(ull a, ull b) {
    ull d; asm("mul.rn.f32x2 %0, %1, %2;" : "=l"(d) : "l"(a), "l"(b)); return d;
}
__device__ __forceinline__ ull pack2q(float a, float b) {
    ull r; asm("mov.b64 %0, {%1, %2};" : "=l"(r) : "f"(a), "f"(b)); return r;
}
__device__ __forceinline__ float2 unpack2q(ull v) {
    float2 r; asm("mov.b64 {%0, %1}, %2;" : "=f"(r.x), "=f"(r.y) : "l"(v)); return r;
}

// ---------------------------------------------------------------------------
// A pre-pass: fp16 convert + k-permute (pair granularity: pairs stay adjacent)
// pair q within 8: q -> (q&3)*2 + (q>>2)
// ---------------------------------------------------------------------------
__global__ void __launch_bounds__(256) around16_kernel(const float* __restrict__ H) {
    size_t row = blockIdx.x;
    const float2* src = (const float2*)(H + row * KK);
    __half2* dst = (__half2*)(g_a16 + row * KK);
#pragma unroll
    for (int r = 0; r < 2; r++) {
        int p = threadIdx.x + r * 256;            // pair index 0..511
        int grp = p >> 3, q = p & 7;
        int pq = (q & 3) * 2 + (q >> 2);
        dst[grp * 8 + pq] = __float22half2_rn(src[p]);
    }
}

// ---------------------------------------------------------------------------
// Weight transpose: Wt16[n][kperm16(k)] = fp16(W[k][n]), zero-padded rows
// ---------------------------------------------------------------------------
__global__ void __launch_bounds__(256) transpose16_kernel(const float* __restrict__ W,
                                                          __half* __restrict__ Wt, int N) {
    __shared__ float tile[32][33];
    int k0 = blockIdx.x * 32, n0 = blockIdx.y * 32;
    int tx = threadIdx.x & 31, ty = threadIdx.x >> 5;   // 32 x 8
#pragma unroll
    for (int i = 0; i < 32; i += 8) {
        int n = n0 + tx;
        tile[ty + i][tx] = (n < N) ? W[(size_t)(k0 + ty + i) * N + n] : 0.f;
    }
    __syncthreads();
#pragma unroll
    for (int i = 0; i < 32; i += 8)
        Wt[(size_t)(n0 + ty + i) * KK + kperm16(k0 + tx)] = __float2half_rn(tile[tx][ty + i]);
}

// ---------------------------------------------------------------------------
// Fused fp16 mma.sync GEMM (cols [0,4128)->qkvba, [4224,6272)->gate)
// CTA 128x128, K-chunk 64, cp.async double buffer, 8 warps (32x64 each)
// Smem rows: 80 halves (160B); banks = 8*gid + 2*tig -> conflict-free LDS.64
// ---------------------------------------------------------------------------
__global__ void __launch_bounds__(256) gemm_mma(const __half* __restrict__ A,
                                                const __half* __restrict__ Bt,
                                                float* __restrict__ C1,
                                                float* __restrict__ C2) {
    extern __shared__ __half smh[];               // [2][A:128x80 | B:128x80]
    uint32_t sbase = smem_u32(smh);

    int tid = threadIdx.x;
    int lane = tid & 31, wid = tid >> 5;
    int gid = lane >> 2, tig = lane & 3;
    int wm = wid & 3, wn = wid >> 2;              // 4 x 2 warp grid
    int m0 = blockIdx.y * 128;
    int n0 = blockIdx.x * 128;

    float acc[2][8][4];
#pragma unroll
    for (int mt = 0; mt < 2; mt++)
#pragma unroll
        for (int nt = 0; nt < 8; nt++)
#pragma unroll
            for (int i = 0; i < 4; i++) acc[mt][nt][i] = 0.f;

    const __half* aBase = A  + (size_t)m0 * KK;
    const __half* bBase = Bt + (size_t)n0 * KK;

    // stage K-chunk of 64 halves (128B per row)
    auto load_tile = [&](int ch, int b) {
        uint32_t a_dst = sbase + b * 40960u;
        uint32_t b_dst = a_dst + 20480u;
        const __half* aS = aBase + ch * 64;
        const __half* bS = bBase + ch * 64;
#pragma unroll
        for (int i = 0; i < 4; i++) {
            int id = tid + 256 * i;
            int row = id >> 3, seg = id & 7;
            cpa16(a_dst + row * 160u + seg * 16u, aS + (size_t)row * KK + seg * 8);
            cpa16(b_dst + row * 160u + seg * 16u, bS + (size_t)row * KK + seg * 8);
        }
        cpa_commit();
    };

    load_tile(0, 0);
    for (int ch = 0; ch < KK / 64; ch++) {
        if (ch + 1 < KK / 64) {
            load_tile(ch + 1, (ch + 1) & 1);
            asm volatile("cp.async.wait_group 1;" ::: "memory");
        } else {
            asm volatile("cp.async.wait_group 0;" ::: "memory");
        }
        __syncthreads();

        const __half* As_h = smh + (ch & 1) * 20480;   // halves
        const __half* Bs_h = As_h + 10240;
        // per-lane base offsets (in halves): row*80 + ks*16 + tig*4
        const __half* aW = As_h + (wm * 32 + gid) * 80 + tig * 4;
        const __half* bW = Bs_h + (wn * 64 + gid) * 80 + tig * 4;

#pragma unroll
        for (int ks = 0; ks < 4; ks++) {
            uint32_t af[2][4];
#pragma unroll
            for (int mt = 0; mt < 2; mt++) {
                uint2 r0 = *(const uint2*)(aW + (mt * 16) * 80 + ks * 16);
                uint2 r1 = *(const uint2*)(aW + (mt * 16 + 8) * 80 + ks * 16);
                af[mt][0] = r0.x;   // (gid,   2t..2t+1)
                af[mt][1] = r1.x;   // (gid+8, 2t..2t+1)
                af[mt][2] = r0.y;   // (gid,   2t+8..2t+9)
                af[mt][3] = r1.y;   // (gid+8, 2t+8..2t+9)
            }
            uint32_t bf[8][2];
#pragma unroll
            for (int nt = 0; nt < 8; nt++) {
                uint2 v = *(const uint2*)(bW + (nt * 8) * 80 + ks * 16);
                bf[nt][0] = v.x;
                bf[nt][1] = v.y;
            }
#pragma unroll
            for (int mt = 0; mt < 2; mt++)
#pragma unroll
                for (int nt = 0; nt < 8; nt++)
                    mma_f16(acc[mt][nt], af[mt], bf[nt]);
        }
        __syncthreads();
    }

    // routed epilogue
#pragma unroll
    for (int mt = 0; mt < 2; mt++) {
        int row = m0 + wm * 32 + mt * 16 + gid;
#pragma unroll
        for (int nt = 0; nt < 8; nt++) {
            int col = n0 + wn * 64 + nt * 8 + 2 * tig;
            float2 lo = make_float2(acc[mt][nt][0], acc[mt][nt][1]);
            float2 hi = make_float2(acc[mt][nt][2], acc[mt][nt][3]);
            if (col < NDIM1) {
                *(float2*)&C1[(size_t)row * NDIM1 + col] = lo;
                *(float2*)&C1[(size_t)(row + 8) * NDIM1 + col] = hi;
            } else if (col >= N1PAD) {
                int c2 = col - N1PAD;
                *(float2*)&C2[(size_t)row * NDIM2 + c2] = lo;
                *(float2*)&C2[(size_t)(row + 8) * NDIM2 + c2] = hi;
            }
        }
    }
}

// ---------------------------------------------------------------------------
// Prep: causal conv4 + SiLU on q/k/v, l2norm on q/k, beta/exp(g)
// ---------------------------------------------------------------------------
__device__ __forceinline__ float silu_f(float y) { return y / (1.f + expf(-y)); }

__global__ void __launch_bounds__(256) prep_kernel(const float* __restrict__ qw,
                                                   const float* __restrict__ kw,
                                                   const float* __restrict__ vw,
                                                   const float* __restrict__ dtb,
                                                   const float* __restrict__ Alog) {
    __shared__ float sq[1024];
    __shared__ float sk[1024];
    __shared__ float sscale[32];
    int row = blockIdx.x;
    int b = row / TT, t = row % TT;
    int tid = threadIdx.x;
    const float* base = g_qkvba + (size_t)row * NDIM1;

#pragma unroll
    for (int r = 0; r < 4; r++) {
        int c = tid + r * 256;
        float yq = 0.f, yk = 0.f;
#pragma unroll
        for (int i = 0; i < 4; i++) {
            int tt = t - 3 + i;
            if (tt >= 0) {
                const float* xr = base + (size_t)(i - 3) * NDIM1;
                yq = fmaf(xr[c], qw[c * 4 + i], yq);
                yk = fmaf(xr[1024 + c], kw[c * 4 + i], yk);
            }
        }
        sq[c] = silu_f(yq);
        sk[c] = silu_f(yk);
    }
#pragma unroll
    for (int r = 0; r < 8; r++) {
        int cv = tid + r * 256;
        float yv = 0.f;
#pragma unroll
        for (int i = 0; i < 4; i++) {
            int tt = t - 3 + i;
            if (tt >= 0)
                yv = fmaf(base[(size_t)(i - 3) * NDIM1 + 2048 + cv], vw[cv * 4 + i], yv);
        }
        int h = cv >> 7, j = cv & 127;
        g_v[(((size_t)(b * NH + h)) * TT + t) * HV + j] = silu_f(yv);
    }
    __syncthreads();
    if (tid < 16) {
        float s = 0.f;
#pragma unroll
        for (int d = 0; d < 64; d++) { float x = sq[tid * 64 + d]; s = fmaf(x, x, s); }
        sscale[tid] = rsqrtf(s + 1e-6f) * 0.125f;
    } else if (tid < 32) {
        int h = tid - 16;
        float s = 0.f;
#pragma unroll
        for (int d = 0; d < 64; d++) { float x = sk[h * 64 + d]; s = fmaf(x, x, s); }
        sscale[tid] = rsqrtf(s + 1e-6f);
    }
    if (tid < 16) {
        int h = tid;
        float bp = base[4096 + h];
        float ap = base[4112 + h];
        float beta = 1.f / (1.f + expf(-bp));
        float x = ap + dtb[h];
        float sp = (x > 20.f) ? x : log1pf(expf(x));
        float g = -expf(Alog[h]) * sp;
        size_t idx = (size_t)(b * NH + h) * TT + t;
        g_eg[idx] = expf(g);
        g_be[idx] = beta;
    }
    __syncthreads();
#pragma unroll
    for (int r = 0; r < 4; r++) {
        int c = tid + r * 256;
        int h = c >> 6, d = c & 63;
        size_t idx = (((size_t)(b * NH + h)) * TT + t) * DH + d;
        g_q[idx] = sq[c] * sscale[h];
        g_k[idx] = sk[c] * sscale[16 + h];
    }
}

// ---------------------------------------------------------------------------
// Scan: one block per (b,h), 128 threads, thread j owns S[:,j]; f32x2 math.
// 8-step tiles, cp.async double-buffered staging; one barrier per tile.
// ---------------------------------------------------------------------------
#define ST 8   // scan tile

__global__ void __launch_bounds__(128) scan_kernel(float* __restrict__ out) {
    __shared__ __align__(16) float sk[2][ST][64];
    __shared__ __align__(16) float sq[2][ST][64];
    __shared__ __align__(16) float sv[2][ST][128];
    __shared__ __align__(16) float sg[2][ST][128];
    __shared__ __align__(16) float seb[2][2][ST];   // [buf][0=eg,1=be][tt]

    int bh = blockIdx.x;
    int b = bh >> 4, h = bh & 15;
    int j = threadIdx.x;

    const float* kp  = g_k  + (size_t)bh * TT * DH;
    const float* qp  = g_q  + (size_t)bh * TT * DH;
    const float* vp0 = g_v  + (size_t)bh * TT * HV;
    const float* egp = g_eg + (size_t)bh * TT;
    const float* bep = g_be + (size_t)bh * TT;
    const float* gp0 = g_gate + (size_t)b * TT * NDIM2 + h * HV;
    float* op        = out    + (size_t)b * TT * NDIM2 + h * HV + j;

    uint32_t a_sk = smem_u32(&sk[0][0][0]);
    uint32_t a_sq = smem_u32(&sq[0][0][0]);
    uint32_t a_sv = smem_u32(&sv[0][0][0]);
    uint32_t a_sg = smem_u32(&sg[0][0][0]);
    uint32_t a_se = smem_u32(&seb[0][0][0]);

    auto issue_tile = [&](int t0, int buf) {
        int row = j >> 4, seg = j & 15;             // k/q: 8 rows x 16 segs(16B)
        cpa16(a_sk + buf * (ST*64*4) + row * 256 + seg * 16,
              kp + (size_t)(t0 + row) * DH + seg * 4);
        cpa16(a_sq + buf * (ST*64*4) + row * 256 + seg * 16,
              qp + (size_t)(t0 + row) * DH + seg * 4);
#pragma unroll
        for (int r = 0; r < 2; r++) {               // v/g: 8 rows x 32 segs
            int s = j + r * 128;
            int vrow = s >> 5, col = (s & 31) * 4;
            cpa16(a_sv + buf * (ST*128*4) + vrow * 512 + col * 4,
                  vp0 + (size_t)(t0 + vrow) * HV + col);
            cpa16(a_sg + buf * (ST*128*4) + vrow * 512 + col * 4,
                  gp0 + (size_t)(t0 + vrow) * NDIM2 + col);
        }
        if (j < ST)            cpa4(a_se + buf * (2*ST*4) + j * 4,           egp + t0 + j);
        else if (j < 2 * ST)   cpa4(a_se + buf * (2*ST*4) + ST*4 + (j-ST)*4, bep + t0 + j - ST);
        cpa_commit();
    };

    ull S2[32];
#pragma unroll
    for (int d = 0; d < 32; d++) S2[d] = 0ULL;

    issue_tile(0, 0);
    cpa_wait0();
    __syncthreads();

    for (int t0 = 0; t0 < TT; t0 += ST) {
        int cur = (t0 >> 3) & 1;
        if (t0 + ST < TT) issue_tile(t0 + ST, cur ^ 1);

#pragma unroll 2
        for (int tt = 0; tt < ST; tt++) {
            float eg = seb[cur][0][tt], be = seb[cur][1][tt];
            float vcur = sv[cur][tt][j];
            float gcur = sg[cur][tt][j];
            const ulonglong2* k2p = (const ulonglong2*)sk[cur][tt];
            const ulonglong2* q2p = (const ulonglong2*)sq[cur][tt];

            ull a0 = 0, a1 = 0, a2 = 0, a3 = 0;
#pragma unroll
            for (int i = 0; i < 8; i++) {
                ulonglong2 ka = k2p[i];
                ulonglong2 kb = k2p[i + 8];
                a0 = fma2q(ka.x, S2[2 * i],      a0);
                a1 = fma2q(ka.y, S2[2 * i + 1],  a1);
                a2 = fma2q(kb.x, S2[2 * i + 16], a2);
                a3 = fma2q(kb.y, S2[2 * i + 17], a3);
            }
            float2 u0 = unpack2q(a0), u1 = unpack2q(a1), u2 = unpack2q(a2), u3 = unpack2q(a3);
            float kS = ((u0.x + u0.y) + (u1.x + u1.y)) + ((u2.x + u2.y) + (u3.x + u3.y));
            float vnew = (vcur - eg * kS) * be;

            ull eg2 = pack2q(eg, eg);
            ull vn2 = pack2q(vnew, vnew);
            ull o0 = 0, o1 = 0, o2 = 0, o3 = 0;
#pragma unroll
            for (int i = 0; i < 8; i++) {
                ulonglong2 ka = k2p[i],  kb = k2p[i + 8];
                ulonglong2 qa = q2p[i],  qb = q2p[i + 8];
                S2[2 * i]      = fma2q(ka.x, vn2, mul2q(S2[2 * i],      eg2)); o0 = fma2q(qa.x, S2[2 * i],      o0);
                S2[2 * i + 1]  = fma2q(ka.y, vn2, mul2q(S2[2 * i + 1],  eg2)); o1 = fma2q(qa.y, S2[2 * i + 1],  o1);
                S2[2 * i + 16] = fma2q(kb.x, vn2, mul2q(S2[2 * i + 16], eg2)); o2 = fma2q(qb.x, S2[2 * i + 16], o2);
                S2[2 * i + 17] = fma2q(kb.y, vn2, mul2q(S2[2 * i + 17], eg2)); o3 = fma2q(qb.y, S2[2 * i + 17], o3);
            }
            float2 w0 = unpack2q(o0), w1 = unpack2q(o1), w2 = unpack2q(o2), w3 = unpack2q(o3);
            float o = ((w0.x + w0.y) + (w1.x + w1.y)) + ((w2.x + w2.y) + (w3.x + w3.y));

            float sgate = gcur / (1.f + expf(-gcur));
            op[(size_t)(t0 + tt) * NDIM2] = o * sgate;
        }

        if (t0 + ST < TT) cpa_wait0();
        __syncthreads();
    }
}

// ---------------------------------------------------------------------------
extern "C" void kernel_launch(void* const* d_in, const int* in_sizes, int n_in,
                              void* d_out, int out_size) {
    const float* H    = (const float*)d_in[0];
    const float* Win  = (const float*)d_in[1];
    const float* qw   = (const float*)d_in[2];
    const float* kw   = (const float*)d_in[3];
    const float* vw   = (const float*)d_in[4];
    const float* dtb  = (const float*)d_in[5];
    const float* Alog = (const float*)d_in[6];
    const float* Wg   = (const float*)d_in[7];
    float* out = (float*)d_out;

    void *p_wt = nullptr, *p_qkvba = nullptr, *p_gate = nullptr, *p_a = nullptr;
    cudaGetSymbolAddress(&p_wt,    g_wt16);
    cudaGetSymbolAddress(&p_qkvba, g_qkvba);
    cudaGetSymbolAddress(&p_gate,  g_gate);
    cudaGetSymbolAddress(&p_a,     g_a16);
    cudaFuncSetAttribute(gemm_mma, cudaFuncAttributeMaxDynamicSharedMemorySize, GM_SMEM);

    around16_kernel<<<MM, 256>>>(H);
    transpose16_kernel<<<dim3(KK / 32, N1PAD / 32), 256>>>(Win, (__half*)p_wt, NDIM1);
    transpose16_kernel<<<dim3(KK / 32, NDIM2 / 32), 256>>>(
        Wg, (__half*)p_wt + (size_t)N1PAD * KK, NDIM2);

    gemm_mma<<<dim3(NTOT / 128, MM / 128), 256, GM_SMEM>>>(
        (const __half*)p_a, (const __half*)p_wt, (float*)p_qkvba, (float*)p_gate);

    prep_kernel<<<MM, 256>>>(qw, kw, vw, dtb, Alog);
    scan_kernel<<<BB * NH, 128>>>(out);
}

// round 10
// speedup vs baseline: 4.6748x; 1.0961x over previous
#include <cuda_runtime.h>
#include <cuda_fp16.h>
#include <math.h>
#include <cstdint>

// ---------------------------------------------------------------------------
// Problem constants
// ---------------------------------------------------------------------------
#define BB 4
#define TT 4096
#define NH 16
#define DH 64
#define HV 128
#define NDIM1 4128            // 2*KEY_DIM + VALUE_DIM + 2*N_HEADS
#define NDIM2 2048            // N_HEADS * HEAD_V
#define MM (BB*TT)            // 16384
#define KK 1024
#define N1PAD 4224            // 33 * 128 (W_in cols padded)
#define NTOT (N1PAD + NDIM2)  // 6272 combined weight cols

#define GM_SMEM 81920         // 2 buffers x (A 20480B + B 20480B), 160B rows

// ---------------------------------------------------------------------------
// Scratch (no cudaMalloc allowed)
// ---------------------------------------------------------------------------
__device__ float g_qkvba[(size_t)MM * NDIM1];
__device__ float g_gate [(size_t)MM * NDIM2];
__device__ float g_q [(size_t)BB*NH*TT*DH];
__device__ float g_k [(size_t)BB*NH*TT*DH];
__device__ float g_v [(size_t)BB*NH*TT*HV];
__device__ float g_eg[(size_t)BB*NH*TT];
__device__ float g_be[(size_t)BB*NH*TT];
__device__ __half g_a16[(size_t)MM * KK];       // fp16, k-permuted A
__device__ __half g_wt16[(size_t)NTOT * KK];    // fp16, k-permuted W_in^T | W_gate^T

// ---------------------------------------------------------------------------
// Helpers
// ---------------------------------------------------------------------------
__device__ __forceinline__ uint32_t smem_u32(const void* p) {
    uint32_t a;
    asm("{ .reg .u64 t; cvta.to.shared.u64 t, %1; cvt.u32.u64 %0, t; }" : "=r"(a) : "l"(p));
    return a;
}
// fp16 k-permutation within each 16-group: one LDS.64 yields {2t,2t+1,2t+8,2t+9}
__device__ __forceinline__ int kperm16(int k) {
    return (k & ~15) | (((k & 7) >> 1) << 2) | (((k >> 3) & 1) << 1) | (k & 1);
}
__device__ __forceinline__ void cpa16(uint32_t dst, const void* src) {
    asm volatile("cp.async.cg.shared.global [%0], [%1], 16;" :: "r"(dst), "l"(src) : "memory");
}
__device__ __forceinline__ void cpa4(uint32_t dst, const void* src) {
    asm volatile("cp.async.ca.shared.global [%0], [%1], 4;" :: "r"(dst), "l"(src) : "memory");
}
__device__ __forceinline__ void cpa_commit() {
    asm volatile("cp.async.commit_group;" ::: "memory");
}
__device__ __forceinline__ void cpa_wait0() {
    asm volatile("cp.async.wait_group 0;" ::: "memory");
}

// fp16 mma m16n8k16, row.col, f32 accum (base ISA, sm_80+)
__device__ __forceinline__ void mma_f16(float* d, const uint32_t* a, const uint32_t* b) {
    asm volatile(
        "mma.sync.aligned.m16n8k16.row.col.f32.f16.f16.f32 "
        "{%0,%1,%2,%3}, {%4,%5,%6,%7}, {%8,%9}, {%0,%1,%2,%3};"
        : "+f"(d[0]), "+f"(d[1]), "+f"(d[2]), "+f"(d[3])
        : "r"(a[0]), "r"(a[1]), "r"(a[2]), "r"(a[3]), "r"(b[0]), "r"(b[1]));
}

// f32x2 packed math
typedef unsigned long long ull;
__device__ __forceinline__ ull fma2q(ull a, ull b, ull c) {
    ull d; asm("fma.rn.f32x2 %0, %1, %2, %3;" : "=l"(d) : "l"(a), "l"(b), "l"(c)); return d;
}
__device__ __forceinline__ ull mul2q(ull a, ull b) {
    ull d; asm("mul.rn.f32x2 %0, %1, %2;" : "=l"(d) : "l"(a), "l"(b)); return d;
}
__device__ __forceinline__ ull pack2q(float a, float b) {
    ull r; asm("mov.b64 %0, {%1, %2};" : "=l"(r) : "f"(a), "f"(b)); return r;
}
__device__ __forceinline__ float2 unpack2q(ull v) {
    float2 r; asm("mov.b64 {%0, %1}, %2;" : "=f"(r.x), "=f"(r.y) : "l"(v)); return r;
}
__device__ __forceinline__ float shfl_bfly1(float v) {
    float r;
    asm volatile("shfl.sync.bfly.b32 %0, %1, 1, 0x1f, 0xffffffff;" : "=f"(r) : "f"(v));
    return r;
}

// ---------------------------------------------------------------------------
// A pre-pass: fp16 convert + k-permute (pair granularity)
// ---------------------------------------------------------------------------
__global__ void __launch_bounds__(256) around16_kernel(const float* __restrict__ H) {
    size_t row = blockIdx.x;
    const float2* src = (const float2*)(H + row * KK);
    __half2* dst = (__half2*)(g_a16 + row * KK);
#pragma unroll
    for (int r = 0; r < 2; r++) {
        int p = threadIdx.x + r * 256;            // pair index 0..511
        int grp = p >> 3, q = p & 7;
        int pq = (q & 3) * 2 + (q >> 2);
        dst[grp * 8 + pq] = __float22half2_rn(src[p]);
    }
}

// ---------------------------------------------------------------------------
// Weight transpose: Wt16[n][kperm16(k)] = fp16(W[k][n]), zero-padded rows
// ---------------------------------------------------------------------------
__global__ void __launch_bounds__(256) transpose16_kernel(const float* __restrict__ W,
                                                          __half* __restrict__ Wt, int N) {
    __shared__ float tile[32][33];
    int k0 = blockIdx.x * 32, n0 = blockIdx.y * 32;
    int tx = threadIdx.x & 31, ty = threadIdx.x >> 5;   // 32 x 8
#pragma unroll
    for (int i = 0; i < 32; i += 8) {
        int n = n0 + tx;
        tile[ty + i][tx] = (n < N) ? W[(size_t)(k0 + ty + i) * N + n] : 0.f;
    }
    __syncthreads();
#pragma unroll
    for (int i = 0; i < 32; i += 8)
        Wt[(size_t)(n0 + ty + i) * KK + kperm16(k0 + tx)] = __float2half_rn(tile[tx][ty + i]);
}

// ---------------------------------------------------------------------------
// Fused fp16 mma.sync GEMM (cols [0,4128)->qkvba, [4224,6272)->gate)
// ---------------------------------------------------------------------------
__global__ void __launch_bounds__(256) gemm_mma(const __half* __restrict__ A,
                                                const __half* __restrict__ Bt,
                                                float* __restrict__ C1,
                                                float* __restrict__ C2) {
    extern __shared__ __half smh[];               // [2][A:128x80 | B:128x80]
    uint32_t sbase = smem_u32(smh);

    int tid = threadIdx.x;
    int lane = tid & 31, wid = tid >> 5;
    int gid = lane >> 2, tig = lane & 3;
    int wm = wid & 3, wn = wid >> 2;              // 4 x 2 warp grid
    int m0 = blockIdx.y * 128;
    int n0 = blockIdx.x * 128;

    float acc[2][8][4];
#pragma unroll
    for (int mt = 0; mt < 2; mt++)
#pragma unroll
        for (int nt = 0; nt < 8; nt++)
#pragma unroll
            for (int i = 0; i < 4; i++) acc[mt][nt][i] = 0.f;

    const __half* aBase = A  + (size_t)m0 * KK;
    const __half* bBase = Bt + (size_t)n0 * KK;

    auto load_tile = [&](int ch, int b) {
        uint32_t a_dst = sbase + b * 40960u;
        uint32_t b_dst = a_dst + 20480u;
        const __half* aS = aBase + ch * 64;
        const __half* bS = bBase + ch * 64;
#pragma unroll
        for (int i = 0; i < 4; i++) {
            int id = tid + 256 * i;
            int row = id >> 3, seg = id & 7;
            cpa16(a_dst + row * 160u + seg * 16u, aS + (size_t)row * KK + seg * 8);
            cpa16(b_dst + row * 160u + seg * 16u, bS + (size_t)row * KK + seg * 8);
        }
        cpa_commit();
    };

    load_tile(0, 0);
    for (int ch = 0; ch < KK / 64; ch++) {
        if (ch + 1 < KK / 64) {
            load_tile(ch + 1, (ch + 1) & 1);
            asm volatile("cp.async.wait_group 1;" ::: "memory");
        } else {
            asm volatile("cp.async.wait_group 0;" ::: "memory");
        }
        __syncthreads();

        const __half* As_h = smh + (ch & 1) * 20480;   // halves
        const __half* Bs_h = As_h + 10240;
        const __half* aW = As_h + (wm * 32 + gid) * 80 + tig * 4;
        const __half* bW = Bs_h + (wn * 64 + gid) * 80 + tig * 4;

#pragma unroll
        for (int ks = 0; ks < 4; ks++) {
            uint32_t af[2][4];
#pragma unroll
            for (int mt = 0; mt < 2; mt++) {
                uint2 r0 = *(const uint2*)(aW + (mt * 16) * 80 + ks * 16);
                uint2 r1 = *(const uint2*)(aW + (mt * 16 + 8) * 80 + ks * 16);
                af[mt][0] = r0.x;
                af[mt][1] = r1.x;
                af[mt][2] = r0.y;
                af[mt][3] = r1.y;
            }
            uint32_t bf[8][2];
#pragma unroll
            for (int nt = 0; nt < 8; nt++) {
                uint2 v = *(const uint2*)(bW + (nt * 8) * 80 + ks * 16);
                bf[nt][0] = v.x;
                bf[nt][1] = v.y;
            }
#pragma unroll
            for (int mt = 0; mt < 2; mt++)
#pragma unroll
                for (int nt = 0; nt < 8; nt++)
                    mma_f16(acc[mt][nt], af[mt], bf[nt]);
        }
        __syncthreads();
    }

    // routed epilogue
#pragma unroll
    for (int mt = 0; mt < 2; mt++) {
        int row = m0 + wm * 32 + mt * 16 + gid;
#pragma unroll
        for (int nt = 0; nt < 8; nt++) {
            int col = n0 + wn * 64 + nt * 8 + 2 * tig;
            float2 lo = make_float2(acc[mt][nt][0], acc[mt][nt][1]);
            float2 hi = make_float2(acc[mt][nt][2], acc[mt][nt][3]);
            if (col < NDIM1) {
                *(float2*)&C1[(size_t)row * NDIM1 + col] = lo;
                *(float2*)&C1[(size_t)(row + 8) * NDIM1 + col] = hi;
            } else if (col >= N1PAD) {
                int c2 = col - N1PAD;
                *(float2*)&C2[(size_t)row * NDIM2 + c2] = lo;
                *(float2*)&C2[(size_t)(row + 8) * NDIM2 + c2] = hi;
            }
        }
    }
}

// ---------------------------------------------------------------------------
// Prep: causal conv4 + SiLU on q/k/v, l2norm on q/k, beta/exp(g)
// ---------------------------------------------------------------------------
__device__ __forceinline__ float silu_f(float y) { return y / (1.f + expf(-y)); }

__global__ void __launch_bounds__(256) prep_kernel(const float* __restrict__ qw,
                                                   const float* __restrict__ kw,
                                                   const float* __restrict__ vw,
                                                   const float* __restrict__ dtb,
                                                   const float* __restrict__ Alog) {
    __shared__ float sq[1024];
    __shared__ float sk[1024];
    __shared__ float sscale[32];
    int row = blockIdx.x;
    int b = row / TT, t = row % TT;
    int tid = threadIdx.x;
    const float* base = g_qkvba + (size_t)row * NDIM1;

#pragma unroll
    for (int r = 0; r < 4; r++) {
        int c = tid + r * 256;
        float yq = 0.f, yk = 0.f;
#pragma unroll
        for (int i = 0; i < 4; i++) {
            int tt = t - 3 + i;
            if (tt >= 0) {
                const float* xr = base + (size_t)(i - 3) * NDIM1;
                yq = fmaf(xr[c], qw[c * 4 + i], yq);
                yk = fmaf(xr[1024 + c], kw[c * 4 + i], yk);
            }
        }
        sq[c] = silu_f(yq);
        sk[c] = silu_f(yk);
    }
#pragma unroll
    for (int r = 0; r < 8; r++) {
        int cv = tid + r * 256;
        float yv = 0.f;
#pragma unroll
        for (int i = 0; i < 4; i++) {
            int tt = t - 3 + i;
            if (tt >= 0)
                yv = fmaf(base[(size_t)(i - 3) * NDIM1 + 2048 + cv], vw[cv * 4 + i], yv);
        }
        int h = cv >> 7, j = cv & 127;
        g_v[(((size_t)(b * NH + h)) * TT + t) * HV + j] = silu_f(yv);
    }
    __syncthreads();
    if (tid < 16) {
        float s = 0.f;
#pragma unroll
        for (int d = 0; d < 64; d++) { float x = sq[tid * 64 + d]; s = fmaf(x, x, s); }
        sscale[tid] = rsqrtf(s + 1e-6f) * 0.125f;
    } else if (tid < 32) {
        int h = tid - 16;
        float s = 0.f;
#pragma unroll
        for (int d = 0; d < 64; d++) { float x = sk[h * 64 + d]; s = fmaf(x, x, s); }
        sscale[tid] = rsqrtf(s + 1e-6f);
    }
    if (tid < 16) {
        int h = tid;
        float bp = base[4096 + h];
        float ap = base[4112 + h];
        float beta = 1.f / (1.f + expf(-bp));
        float x = ap + dtb[h];
        float sp = (x > 20.f) ? x : log1pf(expf(x));
        float g = -expf(Alog[h]) * sp;
        size_t idx = (size_t)(b * NH + h) * TT + t;
        g_eg[idx] = expf(g);
        g_be[idx] = beta;
    }
    __syncthreads();
#pragma unroll
    for (int r = 0; r < 4; r++) {
        int c = tid + r * 256;
        int h = c >> 6, d = c & 63;
        size_t idx = (((size_t)(b * NH + h)) * TT + t) * DH + d;
        g_q[idx] = sq[c] * sscale[h];
        g_k[idx] = sk[c] * sscale[16 + h];
    }
}

// ---------------------------------------------------------------------------
// Scan: 128 blocks = (bh, column-half), 128 threads; 2 threads per V-column,
// each owning 32 of 64 d-values (16 f32x2 regs). shfl.bfly(1) reduces the
// d-split partials. 8-step tiles, cp.async double buffered.
// ---------------------------------------------------------------------------
#define ST 8   // scan tile

__global__ void __launch_bounds__(128) scan_kernel(float* __restrict__ out) {
    __shared__ __align__(16) float sk[2][ST][64];
    __shared__ __align__(16) float sq[2][ST][64];
    __shared__ __align__(16) float sv[2][ST][64];
    __shared__ __align__(16) float sg[2][ST][64];
    __shared__ __align__(16) float seb[2][2][ST];   // [buf][0=eg,1=be][tt]

    int blk = blockIdx.x;            // 0..127
    int bh = blk >> 1, cf = blk & 1; // column-half
    int b = bh >> 4, h = bh & 15;
    int j = threadIdx.x;
    int col = j >> 1, sub = j & 1;   // col 0..63 within half, sub = d-half

    const float* kp  = g_k  + (size_t)bh * TT * DH;
    const float* qp  = g_q  + (size_t)bh * TT * DH;
    const float* vp0 = g_v  + (size_t)bh * TT * HV + cf * 64;
    const float* egp = g_eg + (size_t)bh * TT;
    const float* bep = g_be + (size_t)bh * TT;
    const float* gp0 = g_gate + (size_t)b * TT * NDIM2 + h * HV + cf * 64;
    float* op        = out    + (size_t)b * TT * NDIM2 + h * HV + cf * 64 + col;

    uint32_t a_sk = smem_u32(&sk[0][0][0]);
    uint32_t a_sq = smem_u32(&sq[0][0][0]);
    uint32_t a_sv = smem_u32(&sv[0][0][0]);
    uint32_t a_sg = smem_u32(&sg[0][0][0]);
    uint32_t a_se = smem_u32(&seb[0][0][0]);

    // all buffers: 8 rows x 64 floats per tile = 128 x 16B chunks
    auto issue_tile = [&](int t0, int buf) {
        int row = j >> 4, seg = j & 15;
        cpa16(a_sk + buf * (ST*64*4) + row * 256 + seg * 16,
              kp + (size_t)(t0 + row) * DH + seg * 4);
        cpa16(a_sq + buf * (ST*64*4) + row * 256 + seg * 16,
              qp + (size_t)(t0 + row) * DH + seg * 4);
        cpa16(a_sv + buf * (ST*64*4) + row * 256 + seg * 16,
              vp0 + (size_t)(t0 + row) * HV + seg * 4);
        cpa16(a_sg + buf * (ST*64*4) + row * 256 + seg * 16,
              gp0 + (size_t)(t0 + row) * NDIM2 + seg * 4);
        if (j < ST)            cpa4(a_se + buf * (2*ST*4) + j * 4,           egp + t0 + j);
        else if (j < 2 * ST)   cpa4(a_se + buf * (2*ST*4) + ST*4 + (j-ST)*4, bep + t0 + j - ST);
        cpa_commit();
    };

    ull S2[16];
#pragma unroll
    for (int d = 0; d < 16; d++) S2[d] = 0ULL;

    issue_tile(0, 0);
    cpa_wait0();
    __syncthreads();

    for (int t0 = 0; t0 < TT; t0 += ST) {
        int cur = (t0 >> 3) & 1;
        if (t0 + ST < TT) issue_tile(t0 + ST, cur ^ 1);

#pragma unroll 2
        for (int tt = 0; tt < ST; tt++) {
            float eg = seb[cur][0][tt], be = seb[cur][1][tt];
            float vcur = sv[cur][tt][col];
            float gcur = sg[cur][tt][col];
            const ulonglong2* k2p = (const ulonglong2*)&sk[cur][tt][sub * 32];
            const ulonglong2* q2p = (const ulonglong2*)&sq[cur][tt][sub * 32];

            // partial kS over this thread's 32 d-values
            ull a0 = 0, a1 = 0, a2 = 0, a3 = 0;
#pragma unroll
            for (int i = 0; i < 4; i++) {
                ulonglong2 ka = k2p[i];
                ulonglong2 kb = k2p[i + 4];
                a0 = fma2q(ka.x, S2[2 * i],     a0);
                a1 = fma2q(ka.y, S2[2 * i + 1], a1);
                a2 = fma2q(kb.x, S2[2 * i + 8], a2);
                a3 = fma2q(kb.y, S2[2 * i + 9], a3);
            }
            float2 u0 = unpack2q(a0), u1 = unpack2q(a1), u2 = unpack2q(a2), u3 = unpack2q(a3);
            float kS_part = ((u0.x + u0.y) + (u1.x + u1.y)) + ((u2.x + u2.y) + (u3.x + u3.y));
            float kS = kS_part + shfl_bfly1(kS_part);
            float vnew = (vcur - eg * kS) * be;

            ull eg2 = pack2q(eg, eg);
            ull vn2 = pack2q(vnew, vnew);
            ull o0 = 0, o1 = 0, o2 = 0, o3 = 0;
#pragma unroll
            for (int i = 0; i < 4; i++) {
                ulonglong2 ka = k2p[i],  kb = k2p[i + 4];
                ulonglong2 qa = q2p[i],  qb = q2p[i + 4];
                S2[2 * i]     = fma2q(ka.x, vn2, mul2q(S2[2 * i],     eg2)); o0 = fma2q(qa.x, S2[2 * i],     o0);
                S2[2 * i + 1] = fma2q(ka.y, vn2, mul2q(S2[2 * i + 1], eg2)); o1 = fma2q(qa.y, S2[2 * i + 1], o1);
                S2[2 * i + 8] = fma2q(kb.x, vn2, mul2q(S2[2 * i + 8], eg2)); o2 = fma2q(qb.x, S2[2 * i + 8], o2);
                S2[2 * i + 9] = fma2q(kb.y, vn2, mul2q(S2[2 * i + 9], eg2)); o3 = fma2q(qb.y, S2[2 * i + 9], o3);
            }
            float2 w0 = unpack2q(o0), w1 = unpack2q(o1), w2 = unpack2q(o2), w3 = unpack2q(o3);
            float o_part = ((w0.x + w0.y) + (w1.x + w1.y)) + ((w2.x + w2.y) + (w3.x + w3.y));
            float o = o_part + shfl_bfly1(o_part);

            float sgate = gcur / (1.f + expf(-gcur));
            if (sub == 0)
                op[(size_t)(t0 + tt) * NDIM2] = o * sgate;
        }

        if (t0 + ST < TT) cpa_wait0();
        __syncthreads();
    }
}

// ---------------------------------------------------------------------------
extern "C" void kernel_launch(void* const* d_in, const int* in_sizes, int n_in,
                              void* d_out, int out_size) {
    const float* H    = (const float*)d_in[0];
    const float* Win  = (const float*)d_in[1];
    const float* qw   = (const float*)d_in[2];
    const float* kw   = (const float*)d_in[3];
    const float* vw   = (const float*)d_in[4];
    const float* dtb  = (const float*)d_in[5];
    const float* Alog = (const float*)d_in[6];
    const float* Wg   = (const float*)d_in[7];
    float* out = (float*)d_out;

    void *p_wt = nullptr, *p_qkvba = nullptr, *p_gate = nullptr, *p_a = nullptr;
    cudaGetSymbolAddress(&p_wt,    g_wt16);
    cudaGetSymbolAddress(&p_qkvba, g_qkvba);
    cudaGetSymbolAddress(&p_gate,  g_gate);
    cudaGetSymbolAddress(&p_a,     g_a16);
    cudaFuncSetAttribute(gemm_mma, cudaFuncAttributeMaxDynamicSharedMemorySize, GM_SMEM);

    around16_kernel<<<MM, 256>>>(H);
    transpose16_kernel<<<dim3(KK / 32, N1PAD / 32), 256>>>(Win, (__half*)p_wt, NDIM1);
    transpose16_kernel<<<dim3(KK / 32, NDIM2 / 32), 256>>>(
        Wg, (__half*)p_wt + (size_t)N1PAD * KK, NDIM2);

    gemm_mma<<<dim3(NTOT / 128, MM / 128), 256, GM_SMEM>>>(
        (const __half*)p_a, (const __half*)p_wt, (float*)p_qkvba, (float*)p_gate);

    prep_kernel<<<MM, 256>>>(qw, kw, vw, dtb, Alog);
    scan_kernel<<<2 * BB * NH, 128>>>(out);
}

// round 12
// speedup vs baseline: 5.1244x; 1.0962x over previous
#include <cuda_runtime.h>
#include <cuda_fp16.h>
#include <math.h>
#include <cstdint>

// ---------------------------------------------------------------------------
// Problem constants
// ---------------------------------------------------------------------------
#define BB 4
#define TT 4096
#define NH 16
#define DH 64
#define HV 128
#define NDIM1 4128            // 2*KEY_DIM + VALUE_DIM + 2*N_HEADS
#define NDIM2 2048            // N_HEADS * HEAD_V
#define MM (BB*TT)            // 16384
#define KK 1024
#define N1PAD 4224            // 33 * 128 (W_in cols padded)
#define NTOT (N1PAD + NDIM2)  // 6272 combined weight cols

#define GM_SMEM 81920         // 2 buffers x (A 20480B + B 20480B), 160B rows

// ---------------------------------------------------------------------------
// Scratch (no cudaMalloc allowed)
// ---------------------------------------------------------------------------
__device__ float g_qkvba[(size_t)MM * NDIM1];
__device__ float g_gate [(size_t)MM * NDIM2];     // holds silu(gate) after GEMM
__device__ float g_q [(size_t)BB*NH*TT*DH];
__device__ float g_k [(size_t)BB*NH*TT*DH];
__device__ float g_v [(size_t)BB*NH*TT*HV];
__device__ float g_eg[(size_t)BB*NH*TT];
__device__ float g_be[(size_t)BB*NH*TT];
__device__ __half g_a16[(size_t)MM * KK];       // fp16, k-permuted A
__device__ __half g_wt16[(size_t)NTOT * KK];    // fp16, k-permuted W_in^T | W_gate^T

// ---------------------------------------------------------------------------
// Helpers
// ---------------------------------------------------------------------------
__device__ __forceinline__ uint32_t smem_u32(const void* p) {
    uint32_t a;
    asm("{ .reg .u64 t; cvta.to.shared.u64 t, %1; cvt.u32.u64 %0, t; }" : "=r"(a) : "l"(p));
    return a;
}
// fp16 k-permutation within each 16-group: one LDS.64 yields {2t,2t+1,2t+8,2t+9}
__device__ __forceinline__ int kperm16(int k) {
    return (k & ~15) | (((k & 7) >> 1) << 2) | (((k >> 3) & 1) << 1) | (k & 1);
}
__device__ __forceinline__ void cpa16(uint32_t dst, const void* src) {
    asm volatile("cp.async.cg.shared.global [%0], [%1], 16;" :: "r"(dst), "l"(src) : "memory");
}
__device__ __forceinline__ void cpa4(uint32_t dst, const void* src) {
    asm volatile("cp.async.ca.shared.global [%0], [%1], 4;" :: "r"(dst), "l"(src) : "memory");
}
__device__ __forceinline__ void cpa_commit() {
    asm volatile("cp.async.commit_group;" ::: "memory");
}
__device__ __forceinline__ void cpa_wait0() {
    asm volatile("cp.async.wait_group 0;" ::: "memory");
}

// fp16 mma m16n8k16, row.col, f32 accum (base ISA, sm_80+)
__device__ __forceinline__ void mma_f16(float* d, const uint32_t* a, const uint32_t* b) {
    asm volatile(
        "mma.sync.aligned.m16n8k16.row.col.f32.f16.f16.f32 "
        "{%0,%1,%2,%3}, {%4,%5,%6,%7}, {%8,%9}, {%0,%1,%2,%3};"
        : "+f"(d[0]), "+f"(d[1]), "+f"(d[2]), "+f"(d[3])
        : "r"(a[0]), "r"(a[1]), "r"(a[2]), "r"(a[3]), "r"(b[0]), "r"(b[1]));
}

// f32x2 packed math
typedef unsigned long long ull;
__device__ __forceinline__ ull fma2q(ull a, ull b, ull c) {
    ull d; asm("fma.rn.f32x2 %0, %1, %2, %3;" : "=l"(d) : "l"(a), "l"(b), "l"(c)); return d;
}
__device__ __forceinline__ ull mul2q(ull a, ull b) {
    ull d; asm("mul.rn.f32x2 %0, %1, %2;" : "=l"(d) : "l"(a), "l"(b)); return d;
}
__device__ __forceinline__ ull pack2q(float a, float b) {
    ull r; asm("mov.b64 %0, {%1, %2};" : "=l"(r) : "f"(a), "f"(b)); return r;
}
__device__ __forceinline__ float2 unpack2q(ull v) {
    float2 r; asm("mov.b64 {%0, %1}, %2;" : "=f"(r.x), "=f"(r.y) : "l"(v)); return r;
}
__device__ __forceinline__ float shfl_bfly1(float v) {
    float r;
    asm volatile("shfl.sync.bfly.b32 %0, %1, 1, 0x1f, 0xffffffff;" : "=f"(r) : "f"(v));
    return r;
}
__device__ __forceinline__ float silu_f(float y) { return y / (1.f + expf(-y)); }

// ---------------------------------------------------------------------------
// A pre-pass: fp16 convert + k-permute (pair granularity)
// ---------------------------------------------------------------------------
__global__ void __launch_bounds__(256) around16_kernel(const float* __restrict__ H) {
    size_t row = blockIdx.x;
    const float2* src = (const float2*)(H + row * KK);
    __half2* dst = (__half2*)(g_a16 + row * KK);
#pragma unroll
    for (int r = 0; r < 2; r++) {
        int p = threadIdx.x + r * 256;            // pair index 0..511
        int grp = p >> 3, q = p & 7;
        int pq = (q & 3) * 2 + (q >> 2);
        dst[grp * 8 + pq] = __float22half2_rn(src[p]);
    }
}

// ---------------------------------------------------------------------------
// Weight transpose: Wt16[n][kperm16(k)] = fp16(W[k][n]), zero-padded rows
// ---------------------------------------------------------------------------
__global__ void __launch_bounds__(256) transpose16_kernel(const float* __restrict__ W,
                                                          __half* __restrict__ Wt, int N) {
    __shared__ float tile[32][33];
    int k0 = blockIdx.x * 32, n0 = blockIdx.y * 32;
    int tx = threadIdx.x & 31, ty = threadIdx.x >> 5;   // 32 x 8
#pragma unroll
    for (int i = 0; i < 32; i += 8) {
        int n = n0 + tx;
        tile[ty + i][tx] = (n < N) ? W[(size_t)(k0 + ty + i) * N + n] : 0.f;
    }
    __syncthreads();
#pragma unroll
    for (int i = 0; i < 32; i += 8)
        Wt[(size_t)(n0 + ty + i) * KK + kperm16(k0 + tx)] = __float2half_rn(tile[tx][ty + i]);
}

// ---------------------------------------------------------------------------
// Fused fp16 mma.sync GEMM (cols [0,4128)->qkvba, [4224,6272)->silu->gate)
// CTA 128x128, 4 warps (2x2), warp tile 64x64, K-chunk 64, cp.async dbl buffer
// ---------------------------------------------------------------------------
__global__ void __launch_bounds__(128) gemm_mma(const __half* __restrict__ A,
                                                const __half* __restrict__ Bt,
                                                float* __restrict__ C1,
                                                float* __restrict__ C2) {
    extern __shared__ __half smh[];               // [2][A:128x80 | B:128x80]
    uint32_t sbase = smem_u32(smh);

    int tid = threadIdx.x;
    int lane = tid & 31, wid = tid >> 5;          // 4 warps
    int gid = lane >> 2, tig = lane & 3;
    int wm = wid & 1, wn = wid >> 1;              // 2 x 2 warp grid
    int m0 = blockIdx.y * 128;
    int n0 = blockIdx.x * 128;

    float acc[4][8][4];
#pragma unroll
    for (int mt = 0; mt < 4; mt++)
#pragma unroll
        for (int nt = 0; nt < 8; nt++)
#pragma unroll
            for (int i = 0; i < 4; i++) acc[mt][nt][i] = 0.f;

    const __half* aBase = A  + (size_t)m0 * KK;
    const __half* bBase = Bt + (size_t)n0 * KK;

    auto load_tile = [&](int ch, int b) {
        uint32_t a_dst = sbase + b * 40960u;
        uint32_t b_dst = a_dst + 20480u;
        const __half* aS = aBase + ch * 64;
        const __half* bS = bBase + ch * 64;
#pragma unroll
        for (int i = 0; i < 8; i++) {
            int id = tid + 128 * i;
            int row = id >> 3, seg = id & 7;
            cpa16(a_dst + row * 160u + seg * 16u, aS + (size_t)row * KK + seg * 8);
            cpa16(b_dst + row * 160u + seg * 16u, bS + (size_t)row * KK + seg * 8);
        }
        cpa_commit();
    };

    load_tile(0, 0);
    for (int ch = 0; ch < KK / 64; ch++) {
        if (ch + 1 < KK / 64) {
            load_tile(ch + 1, (ch + 1) & 1);
            asm volatile("cp.async.wait_group 1;" ::: "memory");
        } else {
            asm volatile("cp.async.wait_group 0;" ::: "memory");
        }
        __syncthreads();

        const __half* As_h = smh + (ch & 1) * 20480;   // halves
        const __half* Bs_h = As_h + 10240;
        const __half* aW = As_h + (wm * 64 + gid) * 80 + tig * 4;
        const __half* bW = Bs_h + (wn * 64 + gid) * 80 + tig * 4;

#pragma unroll
        for (int ks = 0; ks < 4; ks++) {
            uint32_t af[4][4];
#pragma unroll
            for (int mt = 0; mt < 4; mt++) {
                uint2 r0 = *(const uint2*)(aW + (mt * 16) * 80 + ks * 16);
                uint2 r1 = *(const uint2*)(aW + (mt * 16 + 8) * 80 + ks * 16);
                af[mt][0] = r0.x;
                af[mt][1] = r1.x;
                af[mt][2] = r0.y;
                af[mt][3] = r1.y;
            }
            uint32_t bf[8][2];
#pragma unroll
            for (int nt = 0; nt < 8; nt++) {
                uint2 v = *(const uint2*)(bW + (nt * 8) * 80 + ks * 16);
                bf[nt][0] = v.x;
                bf[nt][1] = v.y;
            }
#pragma unroll
            for (int mt = 0; mt < 4; mt++)
#pragma unroll
                for (int nt = 0; nt < 8; nt++)
                    mma_f16(acc[mt][nt], af[mt], bf[nt]);
        }
        __syncthreads();
    }

    // routed epilogue; gate columns get silu applied here (scan just multiplies)
#pragma unroll
    for (int mt = 0; mt < 4; mt++) {
        int row = m0 + wm * 64 + mt * 16 + gid;
#pragma unroll
        for (int nt = 0; nt < 8; nt++) {
            int col = n0 + wn * 64 + nt * 8 + 2 * tig;
            if (col < NDIM1) {
                *(float2*)&C1[(size_t)row * NDIM1 + col] =
                    make_float2(acc[mt][nt][0], acc[mt][nt][1]);
                *(float2*)&C1[(size_t)(row + 8) * NDIM1 + col] =
                    make_float2(acc[mt][nt][2], acc[mt][nt][3]);
            } else if (col >= N1PAD) {
                int c2 = col - N1PAD;
                *(float2*)&C2[(size_t)row * NDIM2 + c2] =
                    make_float2(silu_f(acc[mt][nt][0]), silu_f(acc[mt][nt][1]));
                *(float2*)&C2[(size_t)(row + 8) * NDIM2 + c2] =
                    make_float2(silu_f(acc[mt][nt][2]), silu_f(acc[mt][nt][3]));
            }
        }
    }
}

// ---------------------------------------------------------------------------
// Prep: causal conv4 + SiLU on q/k/v, l2norm on q/k, beta/exp(g)
// ---------------------------------------------------------------------------
__global__ void __launch_bounds__(256) prep_kernel(const float* __restrict__ qw,
                                                   const float* __restrict__ kw,
                                                   const float* __restrict__ vw,
                                                   const float* __restrict__ dtb,
                                                   const float* __restrict__ Alog) {
    __shared__ float sq[1024];
    __shared__ float sk[1024];
    __shared__ float sscale[32];
    int row = blockIdx.x;
    int b = row / TT, t = row % TT;
    int tid = threadIdx.x;
    const float* base = g_qkvba + (size_t)row * NDIM1;

#pragma unroll
    for (int r = 0; r < 4; r++) {
        int c = tid + r * 256;
        float yq = 0.f, yk = 0.f;
#pragma unroll
        for (int i = 0; i < 4; i++) {
            int tt = t - 3 + i;
            if (tt >= 0) {
                const float* xr = base + (size_t)(i - 3) * NDIM1;
                yq = fmaf(xr[c], qw[c * 4 + i], yq);
                yk = fmaf(xr[1024 + c], kw[c * 4 + i], yk);
            }
        }
        sq[c] = silu_f(yq);
        sk[c] = silu_f(yk);
    }
#pragma unroll
    for (int r = 0; r < 8; r++) {
        int cv = tid + r * 256;
        float yv = 0.f;
#pragma unroll
        for (int i = 0; i < 4; i++) {
            int tt = t - 3 + i;
            if (tt >= 0)
                yv = fmaf(base[(size_t)(i - 3) * NDIM1 + 2048 + cv], vw[cv * 4 + i], yv);
        }
        int h = cv >> 7, j = cv & 127;
        g_v[(((size_t)(b * NH + h)) * TT + t) * HV + j] = silu_f(yv);
    }
    __syncthreads();
    if (tid < 16) {
        float s = 0.f;
#pragma unroll
        for (int d = 0; d < 64; d++) { float x = sq[tid * 64 + d]; s = fmaf(x, x, s); }
        sscale[tid] = rsqrtf(s + 1e-6f) * 0.125f;
    } else if (tid < 32) {
        int h = tid - 16;
        float s = 0.f;
#pragma unroll
        for (int d = 0; d < 64; d++) { float x = sk[h * 64 + d]; s = fmaf(x, x, s); }
        sscale[tid] = rsqrtf(s + 1e-6f);
    }
    if (tid < 16) {
        int h = tid;
        float bp = base[4096 + h];
        float ap = base[4112 + h];
        float beta = 1.f / (1.f + expf(-bp));
        float x = ap + dtb[h];
        float sp = (x > 20.f) ? x : log1pf(expf(x));
        float g = -expf(Alog[h]) * sp;
        size_t idx = (size_t)(b * NH + h) * TT + t;
        g_eg[idx] = expf(g);
        g_be[idx] = beta;
    }
    __syncthreads();
#pragma unroll
    for (int r = 0; r < 4; r++) {
        int c = tid + r * 256;
        int h = c >> 6, d = c & 63;
        size_t idx = (((size_t)(b * NH + h)) * TT + t) * DH + d;
        g_q[idx] = sq[c] * sscale[h];
        g_k[idx] = sk[c] * sscale[16 + h];
    }
}

// ---------------------------------------------------------------------------
// Scan: 128 blocks = (bh, column-half), 128 threads; 2 threads per V-column,
// each owning 32 of 64 d-values. shfl.bfly(1) reduces the d-split partials.
// 8-step tiles, cp.async double buffered. Gate is pre-silu'd by the GEMM.
// ---------------------------------------------------------------------------
#define ST 8   // scan tile

__global__ void __launch_bounds__(128) scan_kernel(float* __restrict__ out) {
    __shared__ __align__(16) float sk[2][ST][64];
    __shared__ __align__(16) float sq[2][ST][64];
    __shared__ __align__(16) float sv[2][ST][64];
    __shared__ __align__(16) float sg[2][ST][64];
    __shared__ __align__(16) float seb[2][2][ST];   // [buf][0=eg,1=be][tt]

    int blk = blockIdx.x;            // 0..127
    int bh = blk >> 1, cf = blk & 1; // column-half
    int b = bh >> 4, h = bh & 15;
    int j = threadIdx.x;
    int col = j >> 1, sub = j & 1;   // col 0..63 within half, sub = d-half

    const float* kp  = g_k  + (size_t)bh * TT * DH;
    const float* qp  = g_q  + (size_t)bh * TT * DH;
    const float* vp0 = g_v  + (size_t)bh * TT * HV + cf * 64;
    const float* egp = g_eg + (size_t)bh * TT;
    const float* bep = g_be + (size_t)bh * TT;
    const float* gp0 = g_gate + (size_t)b * TT * NDIM2 + h * HV + cf * 64;
    float* op        = out    + (size_t)b * TT * NDIM2 + h * HV + cf * 64 + col;

    uint32_t a_sk = smem_u32(&sk[0][0][0]);
    uint32_t a_sq = smem_u32(&sq[0][0][0]);
    uint32_t a_sv = smem_u32(&sv[0][0][0]);
    uint32_t a_sg = smem_u32(&sg[0][0][0]);
    uint32_t a_se = smem_u32(&seb[0][0][0]);

    auto issue_tile = [&](int t0, int buf) {
        int row = j >> 4, seg = j & 15;
        cpa16(a_sk + buf * (ST*64*4) + row * 256 + seg * 16,
              kp + (size_t)(t0 + row) * DH + seg * 4);
        cpa16(a_sq + buf * (ST*64*4) + row * 256 + seg * 16,
              qp + (size_t)(t0 + row) * DH + seg * 4);
        cpa16(a_sv + buf * (ST*64*4) + row * 256 + seg * 16,
              vp0 + (size_t)(t0 + row) * HV + seg * 4);
        cpa16(a_sg + buf * (ST*64*4) + row * 256 + seg * 16,
              gp0 + (size_t)(t0 + row) * NDIM2 + seg * 4);
        if (j < ST)            cpa4(a_se + buf * (2*ST*4) + j * 4,           egp + t0 + j);
        else if (j < 2 * ST)   cpa4(a_se + buf * (2*ST*4) + ST*4 + (j-ST)*4, bep + t0 + j - ST);
        cpa_commit();
    };

    ull S2[16];
#pragma unroll
    for (int d = 0; d < 16; d++) S2[d] = 0ULL;

    issue_tile(0, 0);
    cpa_wait0();
    __syncthreads();

    for (int t0 = 0; t0 < TT; t0 += ST) {
        int cur = (t0 >> 3) & 1;
        if (t0 + ST < TT) issue_tile(t0 + ST, cur ^ 1);

#pragma unroll 2
        for (int tt = 0; tt < ST; tt++) {
            float eg = seb[cur][0][tt], be = seb[cur][1][tt];
            float vcur = sv[cur][tt][col];
            float gcur = sg[cur][tt][col];       // already silu(gate)
            const ulonglong2* k2p = (const ulonglong2*)&sk[cur][tt][sub * 32];
            const ulonglong2* q2p = (const ulonglong2*)&sq[cur][tt][sub * 32];

            ull a0 = 0, a1 = 0, a2 = 0, a3 = 0;
#pragma unroll
            for (int i = 0; i < 4; i++) {
                ulonglong2 ka = k2p[i];
                ulonglong2 kb = k2p[i + 4];
                a0 = fma2q(ka.x, S2[2 * i],     a0);
                a1 = fma2q(ka.y, S2[2 * i + 1], a1);
                a2 = fma2q(kb.x, S2[2 * i + 8], a2);
                a3 = fma2q(kb.y, S2[2 * i + 9], a3);
            }
            float2 u0 = unpack2q(a0), u1 = unpack2q(a1), u2 = unpack2q(a2), u3 = unpack2q(a3);
            float kS_part = ((u0.x + u0.y) + (u1.x + u1.y)) + ((u2.x + u2.y) + (u3.x + u3.y));
            float kS = kS_part + shfl_bfly1(kS_part);
            float vnew = (vcur - eg * kS) * be;

            ull eg2 = pack2q(eg, eg);
            ull vn2 = pack2q(vnew, vnew);
            ull o0 = 0, o1 = 0, o2 = 0, o3 = 0;
#pragma unroll
            for (int i = 0; i < 4; i++) {
                ulonglong2 ka = k2p[i],  kb = k2p[i + 4];
                ulonglong2 qa = q2p[i],  qb = q2p[i + 4];
                S2[2 * i]     = fma2q(ka.x, vn2, mul2q(S2[2 * i],     eg2)); o0 = fma2q(qa.x, S2[2 * i],     o0);
                S2[2 * i + 1] = fma2q(ka.y, vn2, mul2q(S2[2 * i + 1], eg2)); o1 = fma2q(qa.y, S2[2 * i + 1], o1);
                S2[2 * i + 8] = fma2q(kb.x, vn2, mul2q(S2[2 * i + 8], eg2)); o2 = fma2q(qb.x, S2[2 * i + 8], o2);
                S2[2 * i + 9] = fma2q(kb.y, vn2, mul2q(S2[2 * i + 9], eg2)); o3 = fma2q(qb.y, S2[2 * i + 9], o3);
            }
            float2 w0 = unpack2q(o0), w1 = unpack2q(o1), w2 = unpack2q(o2), w3 = unpack2q(o3);
            float o_part = ((w0.x + w0.y) + (w1.x + w1.y)) + ((w2.x + w2.y) + (w3.x + w3.y));
            float o = o_part + shfl_bfly1(o_part);

            if (sub == 0)
                op[(size_t)(t0 + tt) * NDIM2] = o * gcur;
        }

        if (t0 + ST < TT) cpa_wait0();
        __syncthreads();
    }
}

// ---------------------------------------------------------------------------
extern "C" void kernel_launch(void* const* d_in, const int* in_sizes, int n_in,
                              void* d_out, int out_size) {
    const float* H    = (const float*)d_in[0];
    const float* Win  = (const float*)d_in[1];
    const float* qw   = (const float*)d_in[2];
    const float* kw   = (const float*)d_in[3];
    const float* vw   = (const float*)d_in[4];
    const float* dtb  = (const float*)d_in[5];
    const float* Alog = (const float*)d_in[6];
    const float* Wg   = (const float*)d_in[7];
    float* out = (float*)d_out;

    void *p_wt = nullptr, *p_qkvba = nullptr, *p_gate = nullptr, *p_a = nullptr;
    cudaGetSymbolAddress(&p_wt,    g_wt16);
    cudaGetSymbolAddress(&p_qkvba, g_qkvba);
    cudaGetSymbolAddress(&p_gate,  g_gate);
    cudaGetSymbolAddress(&p_a,     g_a16);
    cudaFuncSetAttribute(gemm_mma, cudaFuncAttributeMaxDynamicSharedMemorySize, GM_SMEM);

    around16_kernel<<<MM, 256>>>(H);
    transpose16_kernel<<<dim3(KK / 32, N1PAD / 32), 256>>>(Win, (__half*)p_wt, NDIM1);
    transpose16_kernel<<<dim3(KK / 32, NDIM2 / 32), 256>>>(
        Wg, (__half*)p_wt + (size_t)N1PAD * KK, NDIM2);

    gemm_mma<<<dim3(NTOT / 128, MM / 128), 128, GM_SMEM>>>(
        (const __half*)p_a, (const __half*)p_wt, (float*)p_qkvba, (float*)p_gate);

    prep_kernel<<<MM, 256>>>(qw, kw, vw, dtb, Alog);
    scan_kernel<<<2 * BB * NH, 128>>>(out);
}